// round 2
// baseline (speedup 1.0000x reference)
#include <cuda_runtime.h>
#include <math.h>

#define B_ 32
#define L_ 4096
#define N_ 256
#define NF 2048          // packed complex FFT size (L/2)
#define FBINS 2049       // rfft bins (L/2+1)
#define NT 256
#define NSERIES (B_*N_)

// Scratch (device globals: allocation-free scratch per harness rules)
__device__ float  g_xt[(size_t)B_*N_*L_];   // (B,N,L) transposed input, 128MB
__device__ float2 g_tw[NF/2];               // exp(-2*pi*i*j/2048), j<1024
__device__ float2 g_rot[NF];                // exp(-pi*i*k/2048),  k<2048

// ---------------------------------------------------------------------------
__global__ void init_tables() {
    int i = blockIdx.x * blockDim.x + threadIdx.x;   // 0..2047
    if (i < NF/2) {
        float ang = -6.2831853071795864769f * (float)i / (float)NF;
        float sn, cs; sincosf(ang, &sn, &cs);
        g_tw[i] = make_float2(cs, sn);
    }
    if (i < NF) {
        float ang = -3.1415926535897932385f * (float)i / (float)NF;
        float sn, cs; sincosf(ang, &sn, &cs);
        g_rot[i] = make_float2(cs, sn);
    }
}

// ---------------------------------------------------------------------------
// Tiled transpose: x (B,L,N) -> g_xt (B,N,L)
__global__ void transpose_kernel(const float* __restrict__ x) {
    __shared__ float tile[32][33];
    int b  = blockIdx.z;
    int l0 = blockIdx.x << 5;
    int n0 = blockIdx.y << 5;
    int tx = threadIdx.x, ty = threadIdx.y;   // (32, 8)
    #pragma unroll
    for (int i = 0; i < 32; i += 8) {
        tile[ty + i][tx] = x[((size_t)b * L_ + (l0 + ty + i)) * N_ + n0 + tx];
    }
    __syncthreads();
    #pragma unroll
    for (int i = 0; i < 32; i += 8) {
        g_xt[((size_t)b * N_ + (n0 + ty + i)) * L_ + l0 + tx] = tile[tx][ty + i];
    }
}

// ---------------------------------------------------------------------------
__device__ __forceinline__ float blockAllReduceSum(float v, float* red) {
    #pragma unroll
    for (int o = 16; o > 0; o >>= 1) v += __shfl_down_sync(0xffffffffu, v, o);
    if ((threadIdx.x & 31) == 0) red[threadIdx.x >> 5] = v;
    __syncthreads();
    if (threadIdx.x == 0) {
        float t = red[0];
        #pragma unroll
        for (int i = 1; i < NT/32; i++) t += red[i];
        red[0] = t;
    }
    __syncthreads();
    float r = red[0];
    __syncthreads();
    return r;
}

__device__ __forceinline__ float blockAllReduceMax(float v, float* red) {
    #pragma unroll
    for (int o = 16; o > 0; o >>= 1) v = fmaxf(v, __shfl_down_sync(0xffffffffu, v, o));
    if ((threadIdx.x & 31) == 0) red[threadIdx.x >> 5] = v;
    __syncthreads();
    if (threadIdx.x == 0) {
        float t = red[0];
        #pragma unroll
        for (int i = 1; i < NT/32; i++) t = fmaxf(t, red[i]);
        red[0] = t;
    }
    __syncthreads();
    float r = red[0];
    __syncthreads();
    return r;
}

// ---------------------------------------------------------------------------
// One CTA per (b,n) series.
__global__ __launch_bounds__(NT) void feat_kernel(
    const float* __restrict__ w1, const float* __restrict__ b1v,
    const float* __restrict__ w2, const float* __restrict__ b2v,
    float* __restrict__ out)
{
    __shared__ float  s[L_];         // series; aliased as float2 z[2048] for FFT
    __shared__ float2 tw[NF/2];
    __shared__ float  amp[FBINS];
    __shared__ float  red[NT/32];
    __shared__ float  rv[NT/32];
    __shared__ int    ri[NT/32];
    __shared__ float  topv[9];
    __shared__ int    topi[9];

    const int tid = threadIdx.x;
    const float* __restrict__ src = g_xt + (size_t)blockIdx.x * L_;

    for (int i = tid; i < L_; i += NT) s[i] = src[i];
    for (int i = tid; i < NF/2; i += NT) tw[i] = g_tw[i];
    __syncthreads();

    // ---- mean ----
    float a0 = 0.f;
    for (int i = tid; i < L_; i += NT) a0 += s[i];
    const float mean = blockAllReduceSum(a0, red) * (1.0f / L_);

    // ---- central moments + autocorrelation sums ----
    float d2 = 0.f, d3 = 0.f, d4 = 0.f;
    float acs[5] = {0.f, 0.f, 0.f, 0.f, 0.f};
    const int lags[5] = {1, 3, 6, 12, 24};
    for (int i = tid; i < L_; i += NT) {
        float d  = s[i] - mean;
        float dd = d * d;
        d2 += dd; d3 += dd * d; d4 += dd * dd;
        #pragma unroll
        for (int q = 0; q < 5; q++) {
            int j = i + lags[q];
            if (j < L_) acs[q] += d * (s[j] - mean);
        }
    }
    d2 = blockAllReduceSum(d2, red);
    d3 = blockAllReduceSum(d3, red);
    d4 = blockAllReduceSum(d4, red);
    #pragma unroll
    for (int q = 0; q < 5; q++) acs[q] = blockAllReduceSum(acs[q], red);

    // ---- in-place radix-2 DIF FFT on packed complex z[m] = (x[2m], x[2m+1]) ----
    float2* z = (float2*)s;
    for (int sh = 10; sh >= 0; --sh) {
        const int hs = 1 << sh;
        for (int t = tid; t < NF/2; t += NT) {
            int off = t & (hs - 1);
            int i0  = ((t >> sh) << (sh + 1)) + off;
            float2 a = z[i0], b = z[i0 + hs];
            float2 w = tw[off << (10 - sh)];
            float dr = a.x - b.x, di = a.y - b.y;
            z[i0]      = make_float2(a.x + b.x, a.y + b.y);
            z[i0 + hs] = make_float2(dr * w.x - di * w.y, dr * w.y + di * w.x);
        }
        __syncthreads();
    }
    // Output is bit-reversed: Z[k] lives at z[brev11(k)].

    // ---- unpack real-FFT amplitudes ----
    const float2 Z0 = z[0];
    for (int k = tid; k < FBINS; k += NT) {
        float xr, xi;
        if (k == 0)       { xr = Z0.x + Z0.y; xi = 0.f; }
        else if (k == NF) { xr = Z0.x - Z0.y; xi = 0.f; }
        else {
            float2 Zk = z[__brev((unsigned)k) >> 21];
            float2 Zj = z[__brev((unsigned)(NF - k)) >> 21];
            float er = 0.5f * (Zk.x + Zj.x);
            float ei = 0.5f * (Zk.y - Zj.y);
            float orr = 0.5f * (Zk.y + Zj.y);
            float oi  = -0.5f * (Zk.x - Zj.x);
            float2 w = g_rot[k];
            xr = er + w.x * orr - w.y * oi;
            xi = ei + w.x * oi  + w.y * orr;
        }
        amp[k] = sqrtf(xr * xr + xi * xi);
    }
    __syncthreads();

    // ---- sum & max of amplitudes ----
    float as = 0.f, am = 0.f;
    for (int k = tid; k < FBINS; k += NT) { float v = amp[k]; as += v; am = fmaxf(am, v); }
    const float S      = blockAllReduceSum(as, red);
    const float maxamp = blockAllReduceMax(am, red);

    // ---- top-9 (descending, tie -> lower index) ----
    for (int r = 0; r < 9; ++r) {
        float bv = -1.f; int bi = FBINS;
        for (int k = tid; k < FBINS; k += NT) {
            float v = amp[k];
            if (v > bv || (v == bv && k < bi)) { bv = v; bi = k; }
        }
        #pragma unroll
        for (int o = 16; o > 0; o >>= 1) {
            float ov = __shfl_down_sync(0xffffffffu, bv, o);
            int   oi = __shfl_down_sync(0xffffffffu, bi, o);
            if (ov > bv || (ov == bv && oi < bi)) { bv = ov; bi = oi; }
        }
        if ((tid & 31) == 0) { rv[tid >> 5] = bv; ri[tid >> 5] = bi; }
        __syncthreads();
        if (tid == 0) {
            #pragma unroll
            for (int q = 1; q < NT/32; q++) {
                if (rv[q] > bv || (rv[q] == bv && ri[q] < bi)) { bv = rv[q]; bi = ri[q]; }
            }
            topv[r] = bv; topi[r] = bi;
            amp[bi] = -2.f;   // remove from further consideration
        }
        __syncthreads();
    }

    // ---- gates, aggregation, final top-5 decode, outputs ----
    if (tid == 0) {
        const float var  = d2 / (float)(L_ - 1);
        const float stdv = sqrtf(var);
        const float se   = stdv + 1e-8f;
        const float se2  = se * se;
        const float skew = (d3 / (float)L_) / (se * se2 + 1e-8f);
        const float kurt = (d4 / (float)L_) / (se2 * se2 + 1e-8f) - 3.0f;

        const float total = S / (float)FBINS + 1e-8f;
        float lvlsum0 = topv[0] + topv[1] + topv[2] + topv[3] + topv[4];
        float lvlsum1 = topv[5] + topv[6];
        float lvlsum[3] = {lvlsum0, lvlsum1, topv[7]};
        float g[3];
        float prefix = 0.f;
        #pragma unroll
        for (int l = 0; l < 3; l++) {
            float rr = ((S - prefix) / (float)FBINS) / total;
            float lr = 0.25f * (float)(l + 1);
            float o = b2v[0];
            #pragma unroll
            for (int j = 0; j < 8; j++) {
                float h = rr * w1[j] + lr * w1[8 + j] + b1v[j];
                h = 0.5f * h * (1.0f + erff(h * 0.70710678118654752f));  // exact GELU
                o += h * w2[j];
            }
            g[l] = 1.0f / (1.0f + expf(-o));
            prefix += lvlsum[l];
        }
        const float r1 = g[0], r2 = g[0] * g[1], r3 = g[0] * g[1] * g[2];
        float rf[9] = {1.f, 1.f, 1.f, 1.f, 1.f, r1, r1, r2, r3};
        float cv[9]; int ci[9];
        #pragma unroll
        for (int i = 0; i < 9; i++) { cv[i] = topv[i] * rf[i]; ci[i] = topi[i]; }
        // insertion sort: value desc, index asc on ties (matches jax top_k)
        for (int i = 1; i < 9; i++) {
            float v = cv[i]; int id = ci[i]; int j = i - 1;
            while (j >= 0 && (cv[j] < v || (cv[j] == v && ci[j] > id))) {
                cv[j + 1] = cv[j]; ci[j + 1] = ci[j]; j--;
            }
            cv[j + 1] = v; ci[j + 1] = id;
        }

        const float invden = 1.0f / (maxamp + 2e-8f);  // (max+eps)+eps
        float* op = out + (size_t)blockIdx.x * 19;
        op[0] = mean; op[1] = stdv; op[2] = skew; op[3] = kurt;
        #pragma unroll
        for (int i = 0; i < 5; i++) {
            op[4 + i] = (float)ci[i] * (1.0f / (float)L_);
            op[9 + i] = cv[i] * invden;
        }
        const int lags2[5] = {1, 3, 6, 12, 24};
        #pragma unroll
        for (int q = 0; q < 5; q++)
            op[14 + q] = (acs[q] / (float)(L_ - lags2[q])) / se2;
    }
}

// ---------------------------------------------------------------------------
extern "C" void kernel_launch(void* const* d_in, const int* in_sizes, int n_in,
                              void* d_out, int out_size) {
    const float* x  = (const float*)d_in[0];
    const float* w1 = (const float*)d_in[1];
    const float* b1 = (const float*)d_in[2];
    const float* w2 = (const float*)d_in[3];
    const float* b2 = (const float*)d_in[4];
    float* out = (float*)d_out;

    init_tables<<<8, 256>>>();

    dim3 tb(32, 8);
    dim3 tg(L_ / 32, N_ / 32, B_);
    transpose_kernel<<<tg, tb>>>(x);

    feat_kernel<<<NSERIES, NT>>>(w1, b1, w2, b2, out);
}

// round 3
// speedup vs baseline: 1.3557x; 1.3557x over previous
#include <cuda_runtime.h>
#include <math.h>

#define B_ 32
#define L_ 4096
#define N_ 256
#define NF 2048          // packed complex FFT size (L/2)
#define FBINS 2049       // rfft bins
#define NT 256
#define NSERIES (B_*N_)

__device__ float  g_xt[(size_t)B_*N_*L_];   // (B,N,L) transposed input
__device__ float2 g_tw[NF/2];               // exp(-2*pi*i*j/2048)
__device__ float2 g_rot[NF];                // exp(-pi*i*k/2048)

// ---------------------------------------------------------------------------
__global__ void init_tables() {
    int i = blockIdx.x * blockDim.x + threadIdx.x;
    if (i < NF/2) {
        float ang = -6.2831853071795864769f * (float)i / (float)NF;
        float sn, cs; sincosf(ang, &sn, &cs);
        g_tw[i] = make_float2(cs, sn);
    }
    if (i < NF) {
        float ang = -3.1415926535897932385f * (float)i / (float)NF;
        float sn, cs; sincosf(ang, &sn, &cs);
        g_rot[i] = make_float2(cs, sn);
    }
}

// ---------------------------------------------------------------------------
__global__ void transpose_kernel(const float* __restrict__ x) {
    __shared__ float tile[32][33];
    int b  = blockIdx.z;
    int l0 = blockIdx.x << 5;
    int n0 = blockIdx.y << 5;
    int tx = threadIdx.x, ty = threadIdx.y;   // (32, 8)
    #pragma unroll
    for (int i = 0; i < 32; i += 8)
        tile[ty + i][tx] = x[((size_t)b * L_ + (l0 + ty + i)) * N_ + n0 + tx];
    __syncthreads();
    #pragma unroll
    for (int i = 0; i < 32; i += 8)
        g_xt[((size_t)b * N_ + (n0 + ty + i)) * L_ + l0 + tx] = tile[tx][ty + i];
}

// ---------------------------------------------------------------------------
#define CMUL(rr, ri, ar, ai, w) { float tr_=(ar), ti_=(ai); rr = tr_*w.x - ti_*w.y; ri = tr_*w.y + ti_*w.x; }

// One CTA per (b,n) series.
__global__ __launch_bounds__(NT) void feat_kernel(
    const float* __restrict__ w1, const float* __restrict__ b1v,
    const float* __restrict__ w2, const float* __restrict__ b2v,
    float* __restrict__ out)
{
    __shared__ float  s[4608];     // floats 0..4095: series / FFT z[]; then 256x9 val + 256x9 key lists
    __shared__ float2 tw[NF/2];
    __shared__ float  red[72];

    const int tid  = threadIdx.x;
    const int lane = tid & 31, warp = tid >> 5;
    const float* __restrict__ src = g_xt + (size_t)blockIdx.x * L_;

    // ---- load + fused mean partial ----
    float a0 = 0.f;
    {
        const float4* __restrict__ src4 = (const float4*)src;
        float4* s4 = (float4*)s;
        #pragma unroll
        for (int c = 0; c < 4; ++c) {
            float4 v = src4[tid + 256*c];
            s4[tid + 256*c] = v;
            a0 += (v.x + v.y) + (v.z + v.w);
        }
    }
    for (int i = tid; i < NF/2; i += NT) tw[i] = g_tw[i];

    // mean reduce
    #pragma unroll
    for (int o = 16; o > 0; o >>= 1) a0 += __shfl_down_sync(~0u, a0, o);
    if (lane == 0) red[warp] = a0;
    __syncthreads();
    if (tid == 0) {
        float t = red[0];
        #pragma unroll
        for (int i = 1; i < 8; i++) t += red[i];
        red[64] = t;
    }
    __syncthreads();
    const float mean = red[64] * (1.0f / L_);
    __syncthreads();

    // ---- moments + autocorr from contiguous per-thread chunk ----
    float e[40];
    {
        const int base = tid * 16;
        #pragma unroll
        for (int c = 0; c < 10; ++c) {
            int idx = base + 4*c;
            if (idx < L_) {
                float4 v = *(const float4*)(s + idx);
                e[4*c+0] = v.x - mean; e[4*c+1] = v.y - mean;
                e[4*c+2] = v.z - mean; e[4*c+3] = v.w - mean;
            } else {
                e[4*c+0] = 0.f; e[4*c+1] = 0.f; e[4*c+2] = 0.f; e[4*c+3] = 0.f;
            }
        }
    }
    float acc[8];   // d2 d3 d4 ac1 ac3 ac6 ac12 ac24
    #pragma unroll
    for (int q = 0; q < 8; q++) acc[q] = 0.f;
    #pragma unroll
    for (int i = 0; i < 16; i++) {
        float d = e[i], dd = d*d;
        acc[0] += dd; acc[1] += dd*d; acc[2] += dd*dd;
        acc[3] += d * e[i+1];
        acc[4] += d * e[i+3];
        acc[5] += d * e[i+6];
        acc[6] += d * e[i+12];
        acc[7] += d * e[i+24];
    }
    // batched reduce of 8 values
    #pragma unroll
    for (int q = 0; q < 8; q++) {
        float v = acc[q];
        #pragma unroll
        for (int o = 16; o > 0; o >>= 1) v += __shfl_down_sync(~0u, v, o);
        if (lane == 0) red[q*8 + warp] = v;
    }
    __syncthreads();
    if (tid < 8) {
        float t = 0.f;
        #pragma unroll
        for (int i = 0; i < 8; i++) t += red[tid*8 + i];
        red[64 + tid] = t;
    }
    __syncthreads();
    const float d2 = red[64], d3 = red[65], d4 = red[66];
    float acs[5] = {red[67], red[68], red[69], red[70], red[71]};
    __syncthreads();

    // ---- FFT: 5 fused double radix-2 stages + 1 radix-2 stage (bit-reversed out) ----
    float2* z = (float2*)s;
    #pragma unroll
    for (int sh = 10; sh >= 2; sh -= 2) {
        const int q = 1 << (sh-1);
        #pragma unroll
        for (int u = 0; u < 2; ++u) {
            int t  = tid + u*256;
            int o  = t & (q-1);
            int i0 = ((t >> (sh-1)) << (sh+1)) + o;
            float2 A = z[i0], Bv = z[i0+q], C = z[i0+2*q], D = z[i0+3*q];
            int ti = o << (10-sh);
            float2 wa = tw[ti];
            float2 wb = tw[2*ti];
            float2 wami = make_float2(wa.y, -wa.x);   // wa * (-i)
            float s0r = A.x + C.x,  s0i = A.y + C.y;
            float s2r = Bv.x + D.x, s2i = Bv.y + D.y;
            float s1r, s1i; CMUL(s1r, s1i, A.x - C.x,  A.y - C.y,  wa);
            float s3r, s3i; CMUL(s3r, s3i, Bv.x - D.x, Bv.y - D.y, wami);
            z[i0]       = make_float2(s0r + s2r, s0i + s2i);
            float o1r, o1i; CMUL(o1r, o1i, s0r - s2r, s0i - s2i, wb);
            z[i0+q]     = make_float2(o1r, o1i);
            z[i0+2*q]   = make_float2(s1r + s3r, s1i + s3i);
            float o3r, o3i; CMUL(o3r, o3i, s1r - s3r, s1i - s3i, wb);
            z[i0+3*q]   = make_float2(o3r, o3i);
        }
        __syncthreads();
    }
    #pragma unroll
    for (int u = 0; u < 4; ++u) {
        int t = tid + u*256;
        float2 a = z[2*t], b = z[2*t+1];
        z[2*t]   = make_float2(a.x + b.x, a.y + b.y);
        z[2*t+1] = make_float2(a.x - b.x, a.y - b.y);
    }
    __syncthreads();

    // ---- unpack amplitudes into registers + local sort ----
    float av[9]; int ak[9];
    float Ssum = 0.f, Smax = 0.f;
    const float2 Z0 = z[0];
    #pragma unroll
    for (int j = 0; j < 8; ++j) {
        int k = tid + 256*j;
        float a;
        if (k == 0) {
            a = fabsf(Z0.x + Z0.y);
        } else {
            float2 Zk = z[__brev((unsigned)k) >> 21];
            float2 Zj = z[__brev((unsigned)(NF - k)) >> 21];
            float er  = 0.5f * (Zk.x + Zj.x);
            float ei  = 0.5f * (Zk.y - Zj.y);
            float orr = 0.5f * (Zk.y + Zj.y);
            float oi  = -0.5f * (Zk.x - Zj.x);
            float2 w = g_rot[k];
            float xr = er + w.x * orr - w.y * oi;
            float xi = ei + w.x * oi  + w.y * orr;
            a = sqrtf(xr*xr + xi*xi);
        }
        av[j] = a; ak[j] = k;
        Ssum += a; Smax = fmaxf(Smax, a);
    }
    if (tid == 0) {
        float aN = fabsf(Z0.x - Z0.y);
        av[8] = aN; ak[8] = 2048;
        Ssum += aN; Smax = fmaxf(Smax, aN);
    } else { av[8] = -1.f; ak[8] = 0x3fffffff; }

    // sort av[0..7] descending (tie -> lower index), Batcher 19 CE
    #define CE(i,j) { if (av[i] < av[j] || (av[i]==av[j] && ak[i] > ak[j])) { \
        float tv=av[i]; av[i]=av[j]; av[j]=tv; int tk=ak[i]; ak[i]=ak[j]; ak[j]=tk; } }
    CE(0,1) CE(2,3) CE(4,5) CE(6,7)
    CE(0,2) CE(1,3) CE(4,6) CE(5,7)
    CE(1,2) CE(5,6)
    CE(0,4) CE(1,5) CE(2,6) CE(3,7)
    CE(2,4) CE(3,5)
    CE(1,2) CE(3,4) CE(5,6)
    // insert element 8
    CE(7,8) CE(6,7) CE(5,6) CE(4,5) CE(3,4) CE(2,3) CE(1,2) CE(0,1)
    #undef CE

    // ---- reduce sum & max of amplitudes (also barrier before list spill) ----
    {
        float sv = Ssum, mv = Smax;
        #pragma unroll
        for (int o = 16; o > 0; o >>= 1) {
            sv += __shfl_down_sync(~0u, sv, o);
            mv = fmaxf(mv, __shfl_down_sync(~0u, mv, o));
        }
        if (lane == 0) { red[warp] = sv; red[8+warp] = mv; }
        __syncthreads();
        if (tid == 0) {
            float ts = red[0], tm = red[8];
            #pragma unroll
            for (int i = 1; i < 8; i++) { ts += red[i]; tm = fmaxf(tm, red[8+i]); }
            red[64] = ts; red[65] = tm;
        }
        __syncthreads();
    }
    const float S = red[64], maxamp = red[65];

    // spill sorted lists into s (FFT data is dead now; reduce above was the barrier)
    #pragma unroll
    for (int r = 0; r < 9; ++r) {
        s[tid*9 + r]        = av[r];
        s[2304 + tid*9 + r] = __int_as_float(ak[r]);
    }

    // ---- 9-round head-pointer selection of global top-9 ----
    float topv[9]; int topi[9];
    int p = 0;
    #pragma unroll
    for (int r = 0; r < 9; ++r) {
        float hv = (p < 9) ? s[tid*9 + p] : -2.f;
        int   hk = (p < 9) ? __float_as_int(s[2304 + tid*9 + p]) : 0x3fffffff;
        const int myk = hk;
        #pragma unroll
        for (int o = 16; o > 0; o >>= 1) {
            float ov = __shfl_down_sync(~0u, hv, o);
            int   ok = __shfl_down_sync(~0u, hk, o);
            if (ov > hv || (ov == hv && ok < hk)) { hv = ov; hk = ok; }
        }
        if (lane == 0) { red[warp] = hv; red[8+warp] = __int_as_float(hk); }
        __syncthreads();
        if (tid == 0) {
            float bv = red[0]; int bk = __float_as_int(red[8]);
            #pragma unroll
            for (int i = 1; i < 8; i++) {
                float ov = red[i]; int ok = __float_as_int(red[8+i]);
                if (ov > bv || (ov == bv && ok < bk)) { bv = ov; bk = ok; }
            }
            red[64] = bv; red[65] = __int_as_float(bk);
        }
        __syncthreads();
        const float wv = red[64];
        const int   wk = __float_as_int(red[65]);
        if (myk == wk) p++;
        topv[r] = wv; topi[r] = wk;
        __syncthreads();
    }

    // ---- gates, final top-5 decode, outputs (thread 0) ----
    if (tid == 0) {
        const float var  = d2 / (float)(L_ - 1);
        const float stdv = sqrtf(var);
        const float se   = stdv + 1e-8f;
        const float se2  = se * se;
        const float skew = (d3 / (float)L_) / (se * se2 + 1e-8f);
        const float kurt = (d4 / (float)L_) / (se2 * se2 + 1e-8f) - 3.0f;

        const float total = S / (float)FBINS + 1e-8f;
        float lvlsum[3] = { topv[0]+topv[1]+topv[2]+topv[3]+topv[4],
                            topv[5]+topv[6], topv[7] };
        float g[3]; float prefix = 0.f;
        #pragma unroll
        for (int l = 0; l < 3; l++) {
            float rr = ((S - prefix) / (float)FBINS) / total;
            float lr = 0.25f * (float)(l + 1);
            float o = b2v[0];
            #pragma unroll
            for (int j = 0; j < 8; j++) {
                float h = rr * w1[j] + lr * w1[8 + j] + b1v[j];
                h = 0.5f * h * (1.0f + erff(h * 0.70710678118654752f));
                o += h * w2[j];
            }
            g[l] = 1.0f / (1.0f + expf(-o));
            prefix += lvlsum[l];
        }
        const float r1 = g[0], r2 = g[0]*g[1], r3 = g[0]*g[1]*g[2];
        const float rf[9] = {1.f,1.f,1.f,1.f,1.f, r1, r1, r2, r3};
        float cv[9]; int ci[9];
        #pragma unroll
        for (int i = 0; i < 9; i++) { cv[i] = topv[i]*rf[i]; ci[i] = topi[i]; }
        for (int i = 1; i < 9; i++) {           // value desc, index asc on ties
            float v = cv[i]; int id = ci[i]; int j = i - 1;
            while (j >= 0 && (cv[j] < v || (cv[j] == v && ci[j] > id))) {
                cv[j+1] = cv[j]; ci[j+1] = ci[j]; j--;
            }
            cv[j+1] = v; ci[j+1] = id;
        }

        const float invden = 1.0f / (maxamp + 2e-8f);
        float* op = out + (size_t)blockIdx.x * 19;
        op[0] = mean; op[1] = stdv; op[2] = skew; op[3] = kurt;
        #pragma unroll
        for (int i = 0; i < 5; i++) {
            op[4 + i] = (float)ci[i] * (1.0f / (float)L_);
            op[9 + i] = cv[i] * invden;
        }
        const int lags2[5] = {1, 3, 6, 12, 24};
        #pragma unroll
        for (int q = 0; q < 5; q++)
            op[14 + q] = (acs[q] / (float)(L_ - lags2[q])) / se2;
    }
}

// ---------------------------------------------------------------------------
extern "C" void kernel_launch(void* const* d_in, const int* in_sizes, int n_in,
                              void* d_out, int out_size) {
    const float* x  = (const float*)d_in[0];
    const float* w1 = (const float*)d_in[1];
    const float* b1 = (const float*)d_in[2];
    const float* w2 = (const float*)d_in[3];
    const float* b2 = (const float*)d_in[4];
    float* out = (float*)d_out;

    init_tables<<<8, 256>>>();

    dim3 tb(32, 8);
    dim3 tg(L_ / 32, N_ / 32, B_);
    transpose_kernel<<<tg, tb>>>(x);

    feat_kernel<<<NSERIES, NT>>>(w1, b1, w2, b2, out);
}

// round 4
// speedup vs baseline: 1.3627x; 1.0051x over previous
#include <cuda_runtime.h>
#include <math.h>

#define B_ 32
#define L_ 4096
#define N_ 256
#define NF 2048          // packed complex FFT size (L/2)
#define FBINS 2049       // rfft bins
#define NT 256
#define NSERIES (B_*N_)

__device__ float  g_xt[(size_t)B_*N_*L_];   // (B,N,L) transposed input
__device__ float2 g_tw[NF/2];               // exp(-2*pi*i*j/2048)
__device__ float2 g_rot[NF];                // exp(-pi*i*k/2048)

// ---------------------------------------------------------------------------
__global__ void init_tables() {
    int i = blockIdx.x * blockDim.x + threadIdx.x;
    if (i < NF/2) {
        float ang = -6.2831853071795864769f * (float)i / (float)NF;
        float sn, cs; sincosf(ang, &sn, &cs);
        g_tw[i] = make_float2(cs, sn);
    }
    if (i < NF) {
        float ang = -3.1415926535897932385f * (float)i / (float)NF;
        float sn, cs; sincosf(ang, &sn, &cs);
        g_rot[i] = make_float2(cs, sn);
    }
}

// ---------------------------------------------------------------------------
__global__ void transpose_kernel(const float* __restrict__ x) {
    __shared__ float tile[32][33];
    int b  = blockIdx.z;
    int l0 = blockIdx.x << 5;
    int n0 = blockIdx.y << 5;
    int tx = threadIdx.x, ty = threadIdx.y;   // (32, 8)
    #pragma unroll
    for (int i = 0; i < 32; i += 8)
        tile[ty + i][tx] = x[((size_t)b * L_ + (l0 + ty + i)) * N_ + n0 + tx];
    __syncthreads();
    #pragma unroll
    for (int i = 0; i < 32; i += 8)
        g_xt[((size_t)b * N_ + (n0 + ty + i)) * L_ + l0 + tx] = tile[tx][ty + i];
}

// ---------------------------------------------------------------------------
#define CMUL(rr, ri, ar, ai, w) { float tr_=(ar), ti_=(ai); rr = tr_*w.x - ti_*w.y; ri = tr_*w.y + ti_*w.x; }

// One CTA per (b,n) series.
__global__ __launch_bounds__(NT, 4) void feat_kernel(
    const float* __restrict__ w1, const float* __restrict__ b1v,
    const float* __restrict__ w2, const float* __restrict__ b2v,
    float* __restrict__ out)
{
    __shared__ float  s[4608];     // 0..4095: series / FFT z[]; then per-thread sorted lists
    __shared__ float2 tw[NF/2];    // twiddles during FFT; reused (as floats) for warp lists after
    __shared__ float  red[80];     // [0..63] moment partials, [64..71] ampsum, [72..79] ampmax

    const int tid  = threadIdx.x;
    const int lane = tid & 31, warp = tid >> 5;
    const float* __restrict__ src = g_xt + (size_t)blockIdx.x * L_;
    float* twf = (float*)tw;

    // ---- load + fused mean partial ----
    float a0 = 0.f;
    {
        const float4* __restrict__ src4 = (const float4*)src;
        float4* s4 = (float4*)s;
        #pragma unroll
        for (int c = 0; c < 4; ++c) {
            float4 v = src4[tid + 256*c];
            s4[tid + 256*c] = v;
            a0 += (v.x + v.y) + (v.z + v.w);
        }
    }
    {
        const float4* __restrict__ gt4 = (const float4*)g_tw;
        float4* tw4 = (float4*)tw;
        tw4[tid] = gt4[tid];
        tw4[tid + 256] = gt4[tid + 256];
    }

    // mean reduce (2 syncs)
    #pragma unroll
    for (int o = 16; o > 0; o >>= 1) a0 += __shfl_down_sync(~0u, a0, o);
    if (lane == 0) red[warp] = a0;
    __syncthreads();
    if (tid == 0) {
        float t = red[0];
        #pragma unroll
        for (int i = 1; i < 8; i++) t += red[i];
        red[64] = t;
    }
    __syncthreads();
    const float mean = red[64] * (1.0f / L_);

    // ---- moments + autocorr: 28-float sliding window over contiguous chunk ----
    {
        const int base = tid * 16;
        float w[28];
        #pragma unroll
        for (int c = 0; c < 7; ++c) {
            int idx = base + 4*c;
            if (idx < L_) {
                float4 v = *(const float4*)(s + idx);
                w[4*c+0] = v.x - mean; w[4*c+1] = v.y - mean;
                w[4*c+2] = v.z - mean; w[4*c+3] = v.w - mean;
            } else {
                w[4*c+0] = 0.f; w[4*c+1] = 0.f; w[4*c+2] = 0.f; w[4*c+3] = 0.f;
            }
        }
        float acc[8];
        #pragma unroll
        for (int q = 0; q < 8; q++) acc[q] = 0.f;
        #pragma unroll
        for (int b = 0; b < 4; ++b) {
            #pragma unroll
            for (int t = 0; t < 4; ++t) {
                float d = w[t], dd = d*d;
                acc[0] += dd; acc[1] += dd*d; acc[2] += dd*dd;
                acc[3] += d * w[t+1];
                acc[4] += d * w[t+3];
                acc[5] += d * w[t+6];
                acc[6] += d * w[t+12];
                acc[7] += d * w[t+24];
            }
            if (b < 3) {
                #pragma unroll
                for (int j = 0; j < 24; j++) w[j] = w[j+4];
                int idx = base + 28 + 4*b;
                if (idx < L_) {
                    float4 v = *(const float4*)(s + idx);
                    w[24] = v.x - mean; w[25] = v.y - mean;
                    w[26] = v.z - mean; w[27] = v.w - mean;
                } else {
                    w[24] = 0.f; w[25] = 0.f; w[26] = 0.f; w[27] = 0.f;
                }
            }
        }
        // warp-reduce 8 accumulators; partials persist in red[0..63] until epilogue
        #pragma unroll
        for (int q = 0; q < 8; q++) {
            float v = acc[q];
            #pragma unroll
            for (int o = 16; o > 0; o >>= 1) v += __shfl_down_sync(~0u, v, o);
            if (lane == 0) red[q*8 + warp] = v;
        }
    }
    __syncthreads();   // moment reads of s done; red partials visible; FFT may clobber s

    // ---- FFT: 5 fused double radix-2 stages + 1 radix-2 stage (bit-reversed out) ----
    float2* z = (float2*)s;
    #pragma unroll
    for (int sh = 10; sh >= 2; sh -= 2) {
        const int q = 1 << (sh-1);
        #pragma unroll
        for (int u = 0; u < 2; ++u) {
            int t  = tid + u*256;
            int o  = t & (q-1);
            int i0 = ((t >> (sh-1)) << (sh+1)) + o;
            float2 A = z[i0], Bv = z[i0+q], C = z[i0+2*q], D = z[i0+3*q];
            int ti = o << (10-sh);
            float2 wa = tw[ti];
            float2 wb = tw[2*ti];
            float2 wami = make_float2(wa.y, -wa.x);   // wa * (-i)
            float s0r = A.x + C.x,  s0i = A.y + C.y;
            float s2r = Bv.x + D.x, s2i = Bv.y + D.y;
            float s1r, s1i; CMUL(s1r, s1i, A.x - C.x,  A.y - C.y,  wa);
            float s3r, s3i; CMUL(s3r, s3i, Bv.x - D.x, Bv.y - D.y, wami);
            z[i0]       = make_float2(s0r + s2r, s0i + s2i);
            float o1r, o1i; CMUL(o1r, o1i, s0r - s2r, s0i - s2i, wb);
            z[i0+q]     = make_float2(o1r, o1i);
            z[i0+2*q]   = make_float2(s1r + s3r, s1i + s3i);
            float o3r, o3i; CMUL(o3r, o3i, s1r - s3r, s1i - s3i, wb);
            z[i0+3*q]   = make_float2(o3r, o3i);
        }
        __syncthreads();
    }
    #pragma unroll
    for (int u = 0; u < 4; ++u) {
        int t = tid + u*256;
        float2 a = z[2*t], b = z[2*t+1];
        z[2*t]   = make_float2(a.x + b.x, a.y + b.y);
        z[2*t+1] = make_float2(a.x - b.x, a.y - b.y);
    }
    __syncthreads();

    // ---- unpack amplitudes into registers + local sort ----
    float av[9]; int ak[9];
    float Ssum = 0.f, Smax = 0.f;
    const float2 Z0 = z[0];
    #pragma unroll
    for (int j = 0; j < 8; ++j) {
        int k = tid + 256*j;
        float a;
        if (k == 0) {
            a = fabsf(Z0.x + Z0.y);
        } else {
            float2 Zk = z[__brev((unsigned)k) >> 21];
            float2 Zj = z[__brev((unsigned)(NF - k)) >> 21];
            float er  = 0.5f * (Zk.x + Zj.x);
            float ei  = 0.5f * (Zk.y - Zj.y);
            float orr = 0.5f * (Zk.y + Zj.y);
            float oi  = -0.5f * (Zk.x - Zj.x);
            float2 w = g_rot[k];
            float xr = er + w.x * orr - w.y * oi;
            float xi = ei + w.x * oi  + w.y * orr;
            a = sqrtf(xr*xr + xi*xi);
        }
        av[j] = a; ak[j] = k;
        Ssum += a; Smax = fmaxf(Smax, a);
    }
    if (tid == 0) {
        float aN = fabsf(Z0.x - Z0.y);
        av[8] = aN; ak[8] = 2048;
        Ssum += aN; Smax = fmaxf(Smax, aN);
    } else { av[8] = -1.f; ak[8] = 0x3fffffff; }

    // sort av[0..7] desc (tie -> lower index), Batcher; then insert element 8
    #define CE(i,j) { if (av[i] < av[j] || (av[i]==av[j] && ak[i] > ak[j])) { \
        float tv=av[i]; av[i]=av[j]; av[j]=tv; int tk=ak[i]; ak[i]=ak[j]; ak[j]=tk; } }
    CE(0,1) CE(2,3) CE(4,5) CE(6,7)
    CE(0,2) CE(1,3) CE(4,6) CE(5,7)
    CE(1,2) CE(5,6)
    CE(0,4) CE(1,5) CE(2,6) CE(3,7)
    CE(2,4) CE(3,5)
    CE(1,2) CE(3,4) CE(5,6)
    CE(7,8) CE(6,7) CE(5,6) CE(4,5) CE(3,4) CE(2,3) CE(1,2) CE(0,1)
    #undef CE

    // amp sum/max warp partials (finalized by tid0 in epilogue)
    {
        float sv = Ssum, mv = Smax;
        #pragma unroll
        for (int o = 16; o > 0; o >>= 1) {
            sv += __shfl_down_sync(~0u, sv, o);
            mv = fmaxf(mv, __shfl_down_sync(~0u, mv, o));
        }
        if (lane == 0) { red[64+warp] = sv; red[72+warp] = mv; }
    }
    __syncthreads();   // all unpack reads of z done -> safe to overwrite s with lists

    // spill per-thread sorted lists (each thread touches only its own slots)
    #pragma unroll
    for (int r = 0; r < 9; ++r) {
        s[tid*9 + r]        = av[r];
        s[2304 + tid*9 + r] = __int_as_float(ak[r]);
    }

    // ---- Phase A: warp-local tournament -> warp top-9 (no barriers) ----
    {
        int p = 0;
        #pragma unroll
        for (int r = 0; r < 9; ++r) {
            float hv = (p < 9) ? s[tid*9 + p] : -2.f;
            int   hk = (p < 9) ? __float_as_int(s[2304 + tid*9 + p]) : 0x7fffffff;
            float bv = hv; int bk = hk;
            #pragma unroll
            for (int o = 16; o > 0; o >>= 1) {
                float ov = __shfl_down_sync(~0u, bv, o);
                int   ok = __shfl_down_sync(~0u, bk, o);
                if (ov > bv || (ov == bv && ok < bk)) { bv = ov; bk = ok; }
            }
            int wk = __shfl_sync(~0u, bk, 0);      // winner key (bins unique globally)
            if (hk == wk) p++;
            if (lane == 0) {
                twf[warp*9 + r]       = bv;
                twf[128 + warp*9 + r] = __int_as_float(bk);
            }
        }
    }
    __syncthreads();

    // ---- Phase B: warp 0 merges 8 warp lists -> global top-9 ----
    if (warp == 0) {
        int p = 0;
        #pragma unroll
        for (int r = 0; r < 9; ++r) {
            float hv = (lane < 8 && p < 9) ? twf[lane*9 + p] : -2.f;
            int   hk = (lane < 8 && p < 9) ? __float_as_int(twf[128 + lane*9 + p]) : 0x7fffffff;
            float bv = hv; int bk = hk;
            #pragma unroll
            for (int o = 4; o > 0; o >>= 1) {
                float ov = __shfl_down_sync(~0u, bv, o);
                int   ok = __shfl_down_sync(~0u, bk, o);
                if (ov > bv || (ov == bv && ok < bk)) { bv = ov; bk = ok; }
            }
            int wk = __shfl_sync(~0u, bk, 0);
            if (hk == wk) p++;
            if (lane == 0) {
                twf[256 + r] = bv;
                twf[272 + r] = __int_as_float(bk);
            }
        }
    }
    // tid0 wrote/reads its own data from here on — no barrier needed.

    // ---- epilogue: gates, final top-5 decode, outputs (thread 0) ----
    if (tid == 0) {
        float d2 = 0.f, d3 = 0.f, d4 = 0.f, acs[5] = {0,0,0,0,0};
        float S = 0.f, maxamp = 0.f;
        #pragma unroll
        for (int i = 0; i < 8; i++) {
            d2 += red[0*8+i]; d3 += red[1*8+i]; d4 += red[2*8+i];
            acs[0] += red[3*8+i]; acs[1] += red[4*8+i]; acs[2] += red[5*8+i];
            acs[3] += red[6*8+i]; acs[4] += red[7*8+i];
            S += red[64+i]; maxamp = fmaxf(maxamp, red[72+i]);
        }
        float topv[9]; int topi[9];
        #pragma unroll
        for (int r = 0; r < 9; ++r) {
            topv[r] = twf[256 + r];
            topi[r] = __float_as_int(twf[272 + r]);
        }

        const float var  = d2 / (float)(L_ - 1);
        const float stdv = sqrtf(var);
        const float se   = stdv + 1e-8f;
        const float se2  = se * se;
        const float skew = (d3 / (float)L_) / (se * se2 + 1e-8f);
        const float kurt = (d4 / (float)L_) / (se2 * se2 + 1e-8f) - 3.0f;

        const float total = S / (float)FBINS + 1e-8f;
        float lvlsum[3] = { topv[0]+topv[1]+topv[2]+topv[3]+topv[4],
                            topv[5]+topv[6], topv[7] };
        float g[3]; float prefix = 0.f;
        #pragma unroll
        for (int l = 0; l < 3; l++) {
            float rr = ((S - prefix) / (float)FBINS) / total;
            float lr = 0.25f * (float)(l + 1);
            float o = b2v[0];
            #pragma unroll
            for (int j = 0; j < 8; j++) {
                float h = rr * w1[j] + lr * w1[8 + j] + b1v[j];
                h = 0.5f * h * (1.0f + erff(h * 0.70710678118654752f));
                o += h * w2[j];
            }
            g[l] = 1.0f / (1.0f + expf(-o));
            prefix += lvlsum[l];
        }
        const float r1 = g[0], r2 = g[0]*g[1], r3 = g[0]*g[1]*g[2];
        const float rf[9] = {1.f,1.f,1.f,1.f,1.f, r1, r1, r2, r3};
        float cv[9]; int ci[9];
        #pragma unroll
        for (int i = 0; i < 9; i++) { cv[i] = topv[i]*rf[i]; ci[i] = topi[i]; }
        for (int i = 1; i < 9; i++) {           // value desc, index asc on ties
            float v = cv[i]; int id = ci[i]; int j = i - 1;
            while (j >= 0 && (cv[j] < v || (cv[j] == v && ci[j] > id))) {
                cv[j+1] = cv[j]; ci[j+1] = ci[j]; j--;
            }
            cv[j+1] = v; ci[j+1] = id;
        }

        const float invden = 1.0f / (maxamp + 2e-8f);
        float* op = out + (size_t)blockIdx.x * 19;
        op[0] = mean; op[1] = stdv; op[2] = skew; op[3] = kurt;
        #pragma unroll
        for (int i = 0; i < 5; i++) {
            op[4 + i] = (float)ci[i] * (1.0f / (float)L_);
            op[9 + i] = cv[i] * invden;
        }
        const int lags2[5] = {1, 3, 6, 12, 24};
        #pragma unroll
        for (int q = 0; q < 5; q++)
            op[14 + q] = (acs[q] / (float)(L_ - lags2[q])) / se2;
    }
}

// ---------------------------------------------------------------------------
extern "C" void kernel_launch(void* const* d_in, const int* in_sizes, int n_in,
                              void* d_out, int out_size) {
    const float* x  = (const float*)d_in[0];
    const float* w1 = (const float*)d_in[1];
    const float* b1 = (const float*)d_in[2];
    const float* w2 = (const float*)d_in[3];
    const float* b2 = (const float*)d_in[4];
    float* out = (float*)d_out;

    init_tables<<<8, 256>>>();

    dim3 tb(32, 8);
    dim3 tg(L_ / 32, N_ / 32, B_);
    transpose_kernel<<<tg, tb>>>(x);

    feat_kernel<<<NSERIES, NT>>>(w1, b1, w2, b2, out);
}

// round 6
// speedup vs baseline: 1.5849x; 1.1631x over previous
#include <cuda_runtime.h>
#include <math.h>

#define B_ 32
#define L_ 4096
#define N_ 256
#define NF 2048          // packed complex FFT size (L/2)
#define FBINS 2049       // rfft bins
#define NT 256
#define NSERIES (B_*N_)

__device__ float  g_xt[(size_t)B_*N_*L_];   // (B,N,L) transposed input
__device__ float2 g_tw[NF/2];               // exp(-2*pi*i*j/2048)
__device__ float2 g_rot[NF];                // exp(-pi*i*k/2048)

// XOR swizzle on float2 indices: conflict-free smem FFT exchanges
#define FZ(a) ((a) ^ (((a) >> 3) & 0xF))

__device__ __forceinline__ float2 cmul(float2 a, float2 b) {
    return make_float2(a.x*b.x - a.y*b.y, a.x*b.y + a.y*b.x);
}
__device__ __forceinline__ float2 cadd(float2 a, float2 b) { return make_float2(a.x+b.x, a.y+b.y); }
__device__ __forceinline__ float2 csub(float2 a, float2 b) { return make_float2(a.x-b.x, a.y-b.y); }
__device__ __forceinline__ float2 cnegi(float2 a) { return make_float2(a.y, -a.x); }  // a * (-i)

// ---------------------------------------------------------------------------
// Tiled transpose x (B,L,N) -> g_xt (B,N,L); block (0,0,0) also fills twiddle tables.
__global__ void transpose_kernel(const float* __restrict__ x) {
    __shared__ float tile[32][33];
    int b  = blockIdx.z;
    int l0 = blockIdx.x << 5;
    int n0 = blockIdx.y << 5;
    int tx = threadIdx.x, ty = threadIdx.y;   // (32, 8)
    if (blockIdx.x == 0 && blockIdx.y == 0 && blockIdx.z == 0) {
        int tid = ty * 32 + tx;
        for (int i = tid; i < NF/2; i += 256) {
            float ang = -6.2831853071795864769f * (float)i / (float)NF;
            float sn, cs; sincosf(ang, &sn, &cs);
            g_tw[i] = make_float2(cs, sn);
        }
        for (int i = tid; i < NF; i += 256) {
            float ang = -3.1415926535897932385f * (float)i / (float)NF;
            float sn, cs; sincosf(ang, &sn, &cs);
            g_rot[i] = make_float2(cs, sn);
        }
    }
    #pragma unroll
    for (int i = 0; i < 32; i += 8)
        tile[ty + i][tx] = x[((size_t)b * L_ + (l0 + ty + i)) * N_ + n0 + tx];
    __syncthreads();
    #pragma unroll
    for (int i = 0; i < 32; i += 8)
        g_xt[((size_t)b * N_ + (n0 + ty + i)) * L_ + l0 + tx] = tile[tx][ty + i];
}

// ---------------------------------------------------------------------------
// radix-4 DIF butterfly (in-place digit placement), twiddles wa = w_S^o, wb = w_{S/2}^o
__device__ __forceinline__ void bfy4(float2* x, float2 wa, float2 wb) {
    float2 wami = cnegi(wa);
    float2 t0 = cadd(x[0], x[2]), u0 = cmul(csub(x[0], x[2]), wa);
    float2 t1 = cadd(x[1], x[3]), u1 = cmul(csub(x[1], x[3]), wami);
    x[0] = cadd(t0, t1); x[1] = cmul(csub(t0, t1), wb);
    x[2] = cadd(u0, u1); x[3] = cmul(csub(u0, u1), wb);
}

// radix-8 DIF butterfly = 3 in-place radix-2 stages on 8 register values.
// wa = w_S^o, wb = w_{S/2}^o, wc = w_{S/4}^o
__device__ __forceinline__ void bfy8(float2* x, float2 wa, float2 wb, float2 wc) {
    const float R2 = 0.70710678118654752440f;
    float2 wa1 = cmul(wa, make_float2(R2, -R2));
    float2 wa2 = cnegi(wa);
    float2 wa3 = cnegi(wa1);
    float2 wbi = cnegi(wb);
    float2 d;
    d = csub(x[0], x[4]); x[0] = cadd(x[0], x[4]); x[4] = cmul(d, wa);
    d = csub(x[1], x[5]); x[1] = cadd(x[1], x[5]); x[5] = cmul(d, wa1);
    d = csub(x[2], x[6]); x[2] = cadd(x[2], x[6]); x[6] = cmul(d, wa2);
    d = csub(x[3], x[7]); x[3] = cadd(x[3], x[7]); x[7] = cmul(d, wa3);
    d = csub(x[0], x[2]); x[0] = cadd(x[0], x[2]); x[2] = cmul(d, wb);
    d = csub(x[1], x[3]); x[1] = cadd(x[1], x[3]); x[3] = cmul(d, wbi);
    d = csub(x[4], x[6]); x[4] = cadd(x[4], x[6]); x[6] = cmul(d, wb);
    d = csub(x[5], x[7]); x[5] = cadd(x[5], x[7]); x[7] = cmul(d, wbi);
    d = csub(x[0], x[1]); x[0] = cadd(x[0], x[1]); x[1] = cmul(d, wc);
    d = csub(x[2], x[3]); x[2] = cadd(x[2], x[3]); x[3] = cmul(d, wc);
    d = csub(x[4], x[5]); x[4] = cadd(x[4], x[5]); x[5] = cmul(d, wc);
    d = csub(x[6], x[7]); x[6] = cadd(x[6], x[7]); x[7] = cmul(d, wc);
}

// ---------------------------------------------------------------------------
// One CTA per (b,n) series.
__global__ __launch_bounds__(NT, 4) void feat_kernel(
    const float* __restrict__ w1, const float* __restrict__ b1v,
    const float* __restrict__ w2, const float* __restrict__ b2v,
    float* __restrict__ out)
{
    __shared__ float s[4608];    // [0,4096): series / FFT z[]; later per-thread sorted lists
    __shared__ float red[304];
    // red layout: [0..71] 9x8 moment partials | [72..79] ampsum | [80..87] ampmax
    //             [88..159] warp-list vals | [160..231] warp-list keys
    //             [232..255] head24 | [256..279] tail24 | [280..297] global top9

    const int tid  = threadIdx.x;
    const int lane = tid & 31, warp = tid >> 5;
    const int lags[5] = {1, 3, 6, 12, 24};

    // ---- phase 1: contiguous load, STS, raw moments in registers ----
    float xl[16];
    {
        const float4* __restrict__ src4 =
            (const float4*)(g_xt + (size_t)blockIdx.x * L_ + tid * 16);
        float4* sm4 = (float4*)s;
        #pragma unroll
        for (int c = 0; c < 4; ++c) {
            float4 v = src4[c];
            sm4[tid*4 + c] = v;
            xl[4*c+0] = v.x; xl[4*c+1] = v.y; xl[4*c+2] = v.z; xl[4*c+3] = v.w;
        }
    }
    if (tid < 8) ((float4*)s)[1024 + tid] = make_float4(0.f, 0.f, 0.f, 0.f); // zero pad [4096..4127]

    // edge stashes (raw values) for autocorr boundary terms
    if (tid == 0) {
        for (int k = 0; k < 16; k++) red[232 + k] = xl[k];
    }
    if (tid == 1) {
        for (int k = 0; k < 8;  k++) red[248 + k] = xl[k];
    }
    if (tid == 254) {
        for (int k = 0; k < 8;  k++) red[256 + k] = xl[8 + k];
    }
    if (tid == 255) {
        for (int k = 0; k < 16; k++) red[264 + k] = xl[k];
    }

    float acc[9];   // s1 s2 s3 s4 R1 R3 R6 R12 R24 (raw sums)
    #pragma unroll
    for (int q = 0; q < 9; q++) acc[q] = 0.f;
    #pragma unroll
    for (int i = 0; i < 16; i++) {
        float v = xl[i], v2 = v*v;
        acc[0] += v; acc[1] += v2; acc[2] += v2*v; acc[3] += v2*v2;
        #pragma unroll
        for (int q = 0; q < 5; q++) {
            int j = i + lags[q];
            if (j < 16) acc[4+q] += v * xl[j];
        }
    }
    __syncthreads();   // sync 1: smem series complete (incl. zero pad)

    // cross-boundary lag products from 24-float tail
    {
        float tl[24];
        const float4* st4 = (const float4*)(s + tid*16 + 16);
        #pragma unroll
        for (int c = 0; c < 6; ++c) {
            float4 v = st4[c];
            tl[4*c+0] = v.x; tl[4*c+1] = v.y; tl[4*c+2] = v.z; tl[4*c+3] = v.w;
        }
        #pragma unroll
        for (int q = 0; q < 5; q++) {
            int l = lags[q];
            #pragma unroll
            for (int k = 0; k < 24; k++) {
                int i = 16 + k - l;
                if (k < l && i >= 0) acc[4+q] += xl[i] * tl[k];
            }
        }
    }
    // warp-reduce 9 raw sums -> red partials (finalized by tid0 at the end)
    #pragma unroll
    for (int q = 0; q < 9; q++) {
        float v = acc[q];
        #pragma unroll
        for (int o = 16; o > 0; o >>= 1) v += __shfl_down_sync(~0u, v, o);
        if (lane == 0) red[q*8 + warp] = v;
    }

    // ---- FFT group 0: radix-4 (S=2048), natural read -> swizzled write ----
    float2* z = (float2*)s;
    float2 xa[4], xb[4];
    #pragma unroll
    for (int j = 0; j < 4; j++) { xa[j] = z[tid + 512*j]; xb[j] = z[tid + 256 + 512*j]; }
    bfy4(xa, g_tw[tid],       g_tw[2*tid]);
    bfy4(xb, g_tw[tid + 256], g_tw[2*tid + 512]);
    __syncthreads();   // sync 2: all natural reads done before swizzled writes
    #pragma unroll
    for (int j = 0; j < 4; j++) {
        z[FZ(tid + 512*j)]       = xa[j];
        z[FZ(tid + 256 + 512*j)] = xb[j];
    }
    __syncthreads();   // sync 3

    float2 zx[8];
    // ---- group 1: radix-8, S=512, q=64 ----
    {
        int o = tid & 63, base = (tid >> 6) * 512 + o;
        #pragma unroll
        for (int j = 0; j < 8; j++) zx[j] = z[FZ(base + 64*j)];
        bfy8(zx, g_tw[4*o], g_tw[8*o], g_tw[16*o]);
        #pragma unroll
        for (int j = 0; j < 8; j++) z[FZ(base + 64*j)] = zx[j];
    }
    __syncthreads();   // sync 4
    // ---- group 2: radix-8, S=64, q=8 ----
    {
        int o = tid & 7, base = (tid >> 3) * 64 + o;
        #pragma unroll
        for (int j = 0; j < 8; j++) zx[j] = z[FZ(base + 8*j)];
        bfy8(zx, g_tw[32*o], g_tw[64*o], g_tw[128*o]);
        #pragma unroll
        for (int j = 0; j < 8; j++) z[FZ(base + 8*j)] = zx[j];
    }
    __syncthreads();   // sync 5
    // ---- group 3: radix-8, S=8, q=1 (unit twiddles) ----
    {
        int base = tid * 8;
        const float2 one = make_float2(1.f, 0.f);
        #pragma unroll
        for (int j = 0; j < 8; j++) zx[j] = z[FZ(base + j)];
        bfy8(zx, one, one, one);
        #pragma unroll
        for (int j = 0; j < 8; j++) z[FZ(base + j)] = zx[j];
    }
    __syncthreads();   // sync 6 — spectrum ready (bit-reversed, swizzled)

    // ---- unpack amplitudes + local sort ----
    float av[9]; int ak[9];
    float Ssum = 0.f, Smax = 0.f;
    const float2 Z0 = z[0];   // FZ(0)==0
    #pragma unroll
    for (int j = 0; j < 8; ++j) {
        int k = tid + 256*j;
        float a;
        if (k == 0) {
            a = fabsf(Z0.x + Z0.y);
        } else {
            float2 Zk = z[FZ(__brev((unsigned)k) >> 21)];
            float2 Zj = z[FZ(__brev((unsigned)(NF - k)) >> 21)];
            float er  = 0.5f * (Zk.x + Zj.x);
            float ei  = 0.5f * (Zk.y - Zj.y);
            float orr = 0.5f * (Zk.y + Zj.y);
            float oi  = -0.5f * (Zk.x - Zj.x);
            float2 w = g_rot[k];
            float xr = er + w.x * orr - w.y * oi;
            float xi = ei + w.x * oi  + w.y * orr;
            a = sqrtf(xr*xr + xi*xi);
        }
        av[j] = a; ak[j] = k;
        Ssum += a; Smax = fmaxf(Smax, a);
    }
    if (tid == 0) {
        float aN = fabsf(Z0.x - Z0.y);
        av[8] = aN; ak[8] = 2048;
        Ssum += aN; Smax = fmaxf(Smax, aN);
    } else { av[8] = -1.f; ak[8] = 0x3fffffff; }

    #define CE(i,j) { if (av[i] < av[j] || (av[i]==av[j] && ak[i] > ak[j])) { \
        float tv=av[i]; av[i]=av[j]; av[j]=tv; int tk=ak[i]; ak[i]=ak[j]; ak[j]=tk; } }
    CE(0,1) CE(2,3) CE(4,5) CE(6,7)
    CE(0,2) CE(1,3) CE(4,6) CE(5,7)
    CE(1,2) CE(5,6)
    CE(0,4) CE(1,5) CE(2,6) CE(3,7)
    CE(2,4) CE(3,5)
    CE(1,2) CE(3,4) CE(5,6)
    CE(7,8) CE(6,7) CE(5,6) CE(4,5) CE(3,4) CE(2,3) CE(1,2) CE(0,1)
    #undef CE

    // amp sum/max warp partials
    {
        float sv = Ssum, mv = Smax;
        #pragma unroll
        for (int o = 16; o > 0; o >>= 1) {
            sv += __shfl_down_sync(~0u, sv, o);
            mv = fmaxf(mv, __shfl_down_sync(~0u, mv, o));
        }
        if (lane == 0) { red[72 + warp] = sv; red[80 + warp] = mv; }
    }
    __syncthreads();   // sync 7: unpack reads done -> safe to overwrite s with lists

    #pragma unroll
    for (int r = 0; r < 9; ++r) {
        s[tid*9 + r]        = av[r];
        s[2304 + tid*9 + r] = __int_as_float(ak[r]);
    }

    // ---- Phase A: warp-local tournament -> warp top-9 ----
    {
        int p = 0;
        #pragma unroll
        for (int r = 0; r < 9; ++r) {
            float hv = (p < 9) ? s[tid*9 + p] : -2.f;
            int   hk = (p < 9) ? __float_as_int(s[2304 + tid*9 + p]) : 0x7fffffff;
            float bv = hv; int bk = hk;
            #pragma unroll
            for (int o = 16; o > 0; o >>= 1) {
                float ov = __shfl_down_sync(~0u, bv, o);
                int   ok = __shfl_down_sync(~0u, bk, o);
                if (ov > bv || (ov == bv && ok < bk)) { bv = ov; bk = ok; }
            }
            int wk = __shfl_sync(~0u, bk, 0);
            if (hk == wk) p++;
            if (lane == 0) {
                red[88  + warp*9 + r] = bv;
                red[160 + warp*9 + r] = __int_as_float(bk);
            }
        }
    }
    __syncthreads();   // sync 8

    // ---- Phase B: warp 0 merges 8 warp lists -> global top-9 ----
    if (warp == 0) {
        int p = 0;
        #pragma unroll
        for (int r = 0; r < 9; ++r) {
            float hv = (lane < 8 && p < 9) ? red[88 + lane*9 + p] : -2.f;
            int   hk = (lane < 8 && p < 9) ? __float_as_int(red[160 + lane*9 + p]) : 0x7fffffff;
            float bv = hv; int bk = hk;
            #pragma unroll
            for (int o = 4; o > 0; o >>= 1) {
                float ov = __shfl_down_sync(~0u, bv, o);
                int   ok = __shfl_down_sync(~0u, bk, o);
                if (ov > bv || (ov == bv && ok < bk)) { bv = ov; bk = ok; }
            }
            int wk = __shfl_sync(~0u, bk, 0);
            if (hk == wk) p++;
            if (lane == 0) {
                red[280 + r] = bv;
                red[289 + r] = __int_as_float(bk);
            }
        }
    }

    // ---- epilogue (thread 0, same warp as Phase B writes) ----
    if (tid == 0) {
        float s1 = 0.f, s2 = 0.f, s3 = 0.f, s4 = 0.f, R[5] = {0,0,0,0,0};
        float S = 0.f, maxamp = 0.f;
        #pragma unroll
        for (int i = 0; i < 8; i++) {
            s1 += red[0*8+i]; s2 += red[1*8+i]; s3 += red[2*8+i]; s4 += red[3*8+i];
            R[0] += red[4*8+i]; R[1] += red[5*8+i]; R[2] += red[6*8+i];
            R[3] += red[7*8+i]; R[4] += red[8*8+i];
            S += red[72+i]; maxamp = fmaxf(maxamp, red[80+i]);
        }
        float topv[9]; int topi[9];
        #pragma unroll
        for (int r = 0; r < 9; ++r) {
            topv[r] = red[280 + r];
            topi[r] = __float_as_int(red[289 + r]);
        }
        // edge prefix/suffix sums
        float H[25], T[25];
        H[0] = 0.f; T[0] = 0.f;
        #pragma unroll
        for (int k = 0; k < 24; k++) {
            H[k+1] = H[k] + red[232 + k];
            T[k+1] = T[k] + red[279 - k];
        }

        const float m  = s1 * (1.0f / L_);
        const float d2 = s2 - (float)L_ * m * m;
        const float d3 = s3 - 3.f*m*s2 + 2.f*(float)L_*m*m*m;
        const float d4 = s4 - 4.f*m*s3 + 6.f*m*m*s2 - 3.f*(float)L_*m*m*m*m;

        const float var  = d2 / (float)(L_ - 1);
        const float stdv = sqrtf(var);
        const float se   = stdv + 1e-8f;
        const float se2  = se * se;
        const float skew = (d3 / (float)L_) / (se * se2 + 1e-8f);
        const float kurt = (d4 / (float)L_) / (se2 * se2 + 1e-8f) - 3.0f;

        const float total = S / (float)FBINS + 1e-8f;
        float lvlsum[3] = { topv[0]+topv[1]+topv[2]+topv[3]+topv[4],
                            topv[5]+topv[6], topv[7] };
        float g[3]; float prefix = 0.f;
        #pragma unroll
        for (int l = 0; l < 3; l++) {
            float rr = ((S - prefix) / (float)FBINS) / total;
            float lr = 0.25f * (float)(l + 1);
            float o = b2v[0];
            #pragma unroll
            for (int j = 0; j < 8; j++) {
                float h = rr * w1[j] + lr * w1[8 + j] + b1v[j];
                h = 0.5f * h * (1.0f + erff(h * 0.70710678118654752f));
                o += h * w2[j];
            }
            g[l] = 1.0f / (1.0f + expf(-o));
            prefix += lvlsum[l];
        }
        const float r1 = g[0], r2 = g[0]*g[1], r3 = g[0]*g[1]*g[2];
        const float rf[9] = {1.f,1.f,1.f,1.f,1.f, r1, r1, r2, r3};
        float cv[9]; int ci[9];
        #pragma unroll
        for (int i = 0; i < 9; i++) { cv[i] = topv[i]*rf[i]; ci[i] = topi[i]; }
        for (int i = 1; i < 9; i++) {           // value desc, index asc on ties
            float v = cv[i]; int id = ci[i]; int j = i - 1;
            while (j >= 0 && (cv[j] < v || (cv[j] == v && ci[j] > id))) {
                cv[j+1] = cv[j]; ci[j+1] = ci[j]; j--;
            }
            cv[j+1] = v; ci[j+1] = id;
        }

        const float invden = 1.0f / (maxamp + 2e-8f);
        float* op = out + (size_t)blockIdx.x * 19;
        op[0] = m; op[1] = stdv; op[2] = skew; op[3] = kurt;
        #pragma unroll
        for (int i = 0; i < 5; i++) {
            op[4 + i] = (float)ci[i] * (1.0f / (float)L_);
            op[9 + i] = cv[i] * invden;
        }
        #pragma unroll
        for (int q = 0; q < 5; q++) {
            int l = lags[q];
            float acsum = R[q] - m * ((s1 - T[l]) + (s1 - H[l])) + (float)(L_ - l) * m * m;
            op[14 + q] = (acsum / (float)(L_ - l)) / se2;
        }
    }
}

// ---------------------------------------------------------------------------
extern "C" void kernel_launch(void* const* d_in, const int* in_sizes, int n_in,
                              void* d_out, int out_size) {
    const float* x  = (const float*)d_in[0];
    const float* w1 = (const float*)d_in[1];
    const float* b1 = (const float*)d_in[2];
    const float* w2 = (const float*)d_in[3];
    const float* b2 = (const float*)d_in[4];
    float* out = (float*)d_out;

    dim3 tb(32, 8);
    dim3 tg(L_ / 32, N_ / 32, B_);
    transpose_kernel<<<tg, tb>>>(x);

    feat_kernel<<<NSERIES, NT>>>(w1, b1, w2, b2, out);
}

// round 7
// speedup vs baseline: 2.0692x; 1.3056x over previous
#include <cuda_runtime.h>
#include <math.h>

#define B_ 32
#define L_ 4096
#define N_ 256
#define NF 2048          // packed complex FFT size (L/2)
#define FBINS 2049       // rfft bins
#define NT 256
#define NSERIES (B_*N_)

__device__ float  g_xt[(size_t)B_*N_*L_];   // (B,N,L) transposed input
__device__ float2 g_tw[NF/2];               // exp(-2*pi*i*j/2048)
__device__ float2 g_rot[NF];                // exp(-pi*i*k/2048)

// XOR swizzle on float2 indices: conflict-free smem FFT exchanges
#define FZ(a) ((a) ^ (((a) >> 3) & 0xF))
// padded natural-order spectrum index
#define YA(k) ((k) + ((k) >> 6))

__device__ __forceinline__ float2 cmul(float2 a, float2 b) {
    return make_float2(a.x*b.x - a.y*b.y, a.x*b.y + a.y*b.x);
}
__device__ __forceinline__ float2 cadd(float2 a, float2 b) { return make_float2(a.x+b.x, a.y+b.y); }
__device__ __forceinline__ float2 csub(float2 a, float2 b) { return make_float2(a.x-b.x, a.y-b.y); }
__device__ __forceinline__ float2 cnegi(float2 a) { return make_float2(a.y, -a.x); }  // a * (-i)

// ---------------------------------------------------------------------------
// Tiled transpose x (B,L,N) -> g_xt (B,N,L); block (0,0,0) also fills twiddle tables.
__global__ void transpose_kernel(const float* __restrict__ x) {
    __shared__ float tile[32][33];
    int b  = blockIdx.z;
    int l0 = blockIdx.x << 5;
    int n0 = blockIdx.y << 5;
    int tx = threadIdx.x, ty = threadIdx.y;   // (32, 8)
    if (blockIdx.x == 0 && blockIdx.y == 0 && blockIdx.z == 0) {
        int tid = ty * 32 + tx;
        for (int i = tid; i < NF/2; i += 256) {
            float ang = -6.2831853071795864769f * (float)i / (float)NF;
            float sn, cs; sincosf(ang, &sn, &cs);
            g_tw[i] = make_float2(cs, sn);
        }
        for (int i = tid; i < NF; i += 256) {
            float ang = -3.1415926535897932385f * (float)i / (float)NF;
            float sn, cs; sincosf(ang, &sn, &cs);
            g_rot[i] = make_float2(cs, sn);
        }
    }
    #pragma unroll
    for (int i = 0; i < 32; i += 8)
        tile[ty + i][tx] = x[((size_t)b * L_ + (l0 + ty + i)) * N_ + n0 + tx];
    __syncthreads();
    #pragma unroll
    for (int i = 0; i < 32; i += 8)
        g_xt[((size_t)b * N_ + (n0 + ty + i)) * L_ + l0 + tx] = tile[tx][ty + i];
}

// ---------------------------------------------------------------------------
// radix-4 DIF butterfly (in-place digit placement), twiddles wa = w_S^o, wb = w_{S/2}^o
__device__ __forceinline__ void bfy4(float2* x, float2 wa, float2 wb) {
    float2 wami = cnegi(wa);
    float2 t0 = cadd(x[0], x[2]), u0 = cmul(csub(x[0], x[2]), wa);
    float2 t1 = cadd(x[1], x[3]), u1 = cmul(csub(x[1], x[3]), wami);
    x[0] = cadd(t0, t1); x[1] = cmul(csub(t0, t1), wb);
    x[2] = cadd(u0, u1); x[3] = cmul(csub(u0, u1), wb);
}

// radix-8 DIF butterfly = 3 in-place radix-2 stages on 8 register values.
__device__ __forceinline__ void bfy8(float2* x, float2 wa, float2 wb, float2 wc) {
    const float R2 = 0.70710678118654752440f;
    float2 wa1 = cmul(wa, make_float2(R2, -R2));
    float2 wa2 = cnegi(wa);
    float2 wa3 = cnegi(wa1);
    float2 wbi = cnegi(wb);
    float2 d;
    d = csub(x[0], x[4]); x[0] = cadd(x[0], x[4]); x[4] = cmul(d, wa);
    d = csub(x[1], x[5]); x[1] = cadd(x[1], x[5]); x[5] = cmul(d, wa1);
    d = csub(x[2], x[6]); x[2] = cadd(x[2], x[6]); x[6] = cmul(d, wa2);
    d = csub(x[3], x[7]); x[3] = cadd(x[3], x[7]); x[7] = cmul(d, wa3);
    d = csub(x[0], x[2]); x[0] = cadd(x[0], x[2]); x[2] = cmul(d, wb);
    d = csub(x[1], x[3]); x[1] = cadd(x[1], x[3]); x[3] = cmul(d, wbi);
    d = csub(x[4], x[6]); x[4] = cadd(x[4], x[6]); x[6] = cmul(d, wb);
    d = csub(x[5], x[7]); x[5] = cadd(x[5], x[7]); x[7] = cmul(d, wbi);
    d = csub(x[0], x[1]); x[0] = cadd(x[0], x[1]); x[1] = cmul(d, wc);
    d = csub(x[2], x[3]); x[2] = cadd(x[2], x[3]); x[3] = cmul(d, wc);
    d = csub(x[4], x[5]); x[4] = cadd(x[4], x[5]); x[5] = cmul(d, wc);
    d = csub(x[6], x[7]); x[6] = cadd(x[6], x[7]); x[7] = cmul(d, wc);
}

// ---------------------------------------------------------------------------
// One CTA per (b,n) series.
__global__ __launch_bounds__(NT, 4) void feat_kernel(
    const float* __restrict__ w1, const float* __restrict__ b1v,
    const float* __restrict__ w2, const float* __restrict__ b2v,
    float* __restrict__ out)
{
    __shared__ float s[4608];    // [0,4096): series / FFT z[]; later per-thread sorted lists
    __shared__ float yr[2080];   // natural-order spectrum real (padded)
    __shared__ float yi[2080];   // natural-order spectrum imag (padded)
    __shared__ float red[304];
    // red layout: [0..71] 9x8 moment partials | [72..79] ampsum | [80..87] ampmax
    //             [88..159] warp-list vals | [160..231] warp-list keys
    //             [232..255] head24 | [256..279] tail24 | [280..297] global top9

    const int tid  = threadIdx.x;
    const int lane = tid & 31, warp = tid >> 5;
    const int lags[5] = {1, 3, 6, 12, 24};

    // ---- phase 1: contiguous load, STS, raw moments in registers ----
    float xl[16];
    {
        const float4* __restrict__ src4 =
            (const float4*)(g_xt + (size_t)blockIdx.x * L_ + tid * 16);
        float4* sm4 = (float4*)s;
        #pragma unroll
        for (int c = 0; c < 4; ++c) {
            float4 v = src4[c];
            sm4[tid*4 + c] = v;
            xl[4*c+0] = v.x; xl[4*c+1] = v.y; xl[4*c+2] = v.z; xl[4*c+3] = v.w;
        }
    }
    if (tid < 8) ((float4*)s)[1024 + tid] = make_float4(0.f, 0.f, 0.f, 0.f); // zero pad

    // edge stashes (raw values) for autocorr boundary terms
    if (tid == 0) {
        for (int k = 0; k < 16; k++) red[232 + k] = xl[k];
    }
    if (tid == 1) {
        for (int k = 0; k < 8;  k++) red[248 + k] = xl[k];
    }
    if (tid == 254) {
        for (int k = 0; k < 8;  k++) red[256 + k] = xl[8 + k];
    }
    if (tid == 255) {
        for (int k = 0; k < 16; k++) red[264 + k] = xl[k];
    }

    float acc[9];   // s1 s2 s3 s4 R1 R3 R6 R12 R24 (raw sums)
    #pragma unroll
    for (int q = 0; q < 9; q++) acc[q] = 0.f;
    #pragma unroll
    for (int i = 0; i < 16; i++) {
        float v = xl[i], v2 = v*v;
        acc[0] += v; acc[1] += v2; acc[2] += v2*v; acc[3] += v2*v2;
        #pragma unroll
        for (int q = 0; q < 5; q++) {
            int j = i + lags[q];
            if (j < 16) acc[4+q] += v * xl[j];
        }
    }
    __syncthreads();   // sync 1: smem series complete (incl. zero pad)

    // cross-boundary lag products from 24-float tail
    {
        float tl[24];
        const float4* st4 = (const float4*)(s + tid*16 + 16);
        #pragma unroll
        for (int c = 0; c < 6; ++c) {
            float4 v = st4[c];
            tl[4*c+0] = v.x; tl[4*c+1] = v.y; tl[4*c+2] = v.z; tl[4*c+3] = v.w;
        }
        #pragma unroll
        for (int q = 0; q < 5; q++) {
            int l = lags[q];
            #pragma unroll
            for (int k = 0; k < 24; k++) {
                int i = 16 + k - l;
                if (k < l && i >= 0) acc[4+q] += xl[i] * tl[k];
            }
        }
    }
    // warp-reduce 9 raw sums -> red partials (finalized by tid0 at the end)
    #pragma unroll
    for (int q = 0; q < 9; q++) {
        float v = acc[q];
        #pragma unroll
        for (int o = 16; o > 0; o >>= 1) v += __shfl_down_sync(~0u, v, o);
        if (lane == 0) red[q*8 + warp] = v;
    }

    // ---- FFT group 0: radix-4 (S=2048), natural read -> swizzled write ----
    float2* z = (float2*)s;
    float2 xa[4], xb[4];
    #pragma unroll
    for (int j = 0; j < 4; j++) { xa[j] = z[tid + 512*j]; xb[j] = z[tid + 256 + 512*j]; }
    bfy4(xa, g_tw[tid],       g_tw[2*tid]);
    bfy4(xb, g_tw[tid + 256], g_tw[2*tid + 512]);
    __syncthreads();   // sync 2
    #pragma unroll
    for (int j = 0; j < 4; j++) {
        z[FZ(tid + 512*j)]       = xa[j];
        z[FZ(tid + 256 + 512*j)] = xb[j];
    }
    __syncthreads();   // sync 3

    float2 zx[8];
    // ---- group 1: radix-8, S=512, q=64 ----
    {
        int o = tid & 63, base = (tid >> 6) * 512 + o;
        #pragma unroll
        for (int j = 0; j < 8; j++) zx[j] = z[FZ(base + 64*j)];
        bfy8(zx, g_tw[4*o], g_tw[8*o], g_tw[16*o]);
        #pragma unroll
        for (int j = 0; j < 8; j++) z[FZ(base + 64*j)] = zx[j];
    }
    __syncthreads();   // sync 4
    // ---- group 2: radix-8, S=64, q=8 ----
    {
        int o = tid & 7, base = (tid >> 3) * 64 + o;
        #pragma unroll
        for (int j = 0; j < 8; j++) zx[j] = z[FZ(base + 8*j)];
        bfy8(zx, g_tw[32*o], g_tw[64*o], g_tw[128*o]);
        #pragma unroll
        for (int j = 0; j < 8; j++) z[FZ(base + 8*j)] = zx[j];
    }
    __syncthreads();   // sync 5
    // ---- group 3: radix-8, S=8, q=1 (unit twiddles) ----
    {
        int base = tid * 8;
        const float2 one = make_float2(1.f, 0.f);
        #pragma unroll
        for (int j = 0; j < 8; j++) zx[j] = z[FZ(base + j)];
        bfy8(zx, one, one, one);
        #pragma unroll
        for (int j = 0; j < 8; j++) z[FZ(base + j)] = zx[j];
    }
    __syncthreads();   // sync 6 — spectrum ready (bit-reversed, swizzled)

    // ---- de-reversal pass: z -> yr/yi in natural bin order (conflict-free both sides) ----
    #pragma unroll
    for (int jj = 0; jj < 8; ++jj) {
        int p = tid + 256*jj;
        float2 v = z[FZ(p)];
        int k = __brev((unsigned)p) >> 21;
        int a = YA(k);
        yr[a] = v.x; yi[a] = v.y;
    }
    __syncthreads();   // sync 7 — natural spectrum ready; z (s) is dead

    // ---- unpack amplitudes via conjugate-pair symmetry + local sort ----
    // X[k] = E + wO ; X[2048-k] = conj(E - wO)  -> two amps per pair, one rot load
    float av[9]; int ak[9];
    float Ssum = 0.f, Smax = 0.f;
    #pragma unroll
    for (int c = 0; c < 4; ++c) {
        int k = 1 + tid + 256*c;          // 1..1024
        int m = 2048 - k;                 // 1024..2047
        int ka = YA(k), ma = YA(m);
        float zkr = yr[ka], zki = yi[ka];
        float zmr = yr[ma], zmi = yi[ma];
        float er  = 0.5f * (zkr + zmr);
        float ei  = 0.5f * (zki - zmi);
        float orr = 0.5f * (zki + zmi);
        float oi  = -0.5f * (zkr - zmr);
        float2 w = g_rot[k];
        float pr = w.x*orr - w.y*oi;
        float pi = w.x*oi  + w.y*orr;
        float xr = er + pr, xi2 = ei + pi;
        float ampk = sqrtf(xr*xr + xi2*xi2);
        float qr = er - pr, qi = ei - pi;
        float ampm = sqrtf(qr*qr + qi*qi);
        av[c] = ampk; ak[c] = k;
        Ssum += ampk; Smax = fmaxf(Smax, ampk);
        if (k == 1024) { av[4+c] = -1.f; ak[4+c] = 0x3fffffff; }  // self-pair dup
        else {
            av[4+c] = ampm; ak[4+c] = m;
            Ssum += ampm; Smax = fmaxf(Smax, ampm);
        }
    }
    av[8] = -1.f; ak[8] = 0x3fffffff;

    float a0 = 0.f, aN = 0.f;
    if (tid == 0) {
        float z0r = yr[0], z0i = yi[0];
        a0 = fabsf(z0r + z0i);            // bin 0
        aN = fabsf(z0r - z0i);            // bin 2048
        Ssum += a0 + aN;
        Smax = fmaxf(Smax, fmaxf(a0, aN));
    }

    // sort av[0..7] desc (tie -> lower index), Batcher 19 CE
    #define CE(i,j) { if (av[i] < av[j] || (av[i]==av[j] && ak[i] > ak[j])) { \
        float tv=av[i]; av[i]=av[j]; av[j]=tv; int tk=ak[i]; ak[i]=ak[j]; ak[j]=tk; } }
    CE(0,1) CE(2,3) CE(4,5) CE(6,7)
    CE(0,2) CE(1,3) CE(4,6) CE(5,7)
    CE(1,2) CE(5,6)
    CE(0,4) CE(1,5) CE(2,6) CE(3,7)
    CE(2,4) CE(3,5)
    CE(1,2) CE(3,4) CE(5,6)
    // tid0: insert bins 0 and 2048 (insert-with-drop keeps thread top-9)
    if (tid == 0) {
        if (a0 > av[8] || (a0 == av[8] && 0 < ak[8])) { av[8] = a0; ak[8] = 0; }
        CE(7,8) CE(6,7) CE(5,6) CE(4,5) CE(3,4) CE(2,3) CE(1,2) CE(0,1)
        if (aN > av[8] || (aN == av[8] && 2048 < ak[8])) { av[8] = aN; ak[8] = 2048; }
        CE(7,8) CE(6,7) CE(5,6) CE(4,5) CE(3,4) CE(2,3) CE(1,2) CE(0,1)
    } else {
        CE(7,8) CE(6,7) CE(5,6) CE(4,5) CE(3,4) CE(2,3) CE(1,2) CE(0,1)
    }
    #undef CE

    // amp sum/max warp partials
    {
        float sv = Ssum, mv = Smax;
        #pragma unroll
        for (int o = 16; o > 0; o >>= 1) {
            sv += __shfl_down_sync(~0u, sv, o);
            mv = fmaxf(mv, __shfl_down_sync(~0u, mv, o));
        }
        if (lane == 0) { red[72 + warp] = sv; red[80 + warp] = mv; }
    }

    // spill per-thread sorted lists into s (z dead since sync 7; no barrier needed
    // because each thread writes only its own slots and readers sync below)
    #pragma unroll
    for (int r = 0; r < 9; ++r) {
        s[tid*9 + r]        = av[r];
        s[2304 + tid*9 + r] = __int_as_float(ak[r]);
    }
    __syncthreads();   // sync 8: lists + amp partials visible

    // ---- Phase A: warp-local tournament -> warp top-9 ----
    {
        int p = 0;
        #pragma unroll
        for (int r = 0; r < 9; ++r) {
            float hv = (p < 9) ? s[tid*9 + p] : -2.f;
            int   hk = (p < 9) ? __float_as_int(s[2304 + tid*9 + p]) : 0x7fffffff;
            float bv = hv; int bk = hk;
            #pragma unroll
            for (int o = 16; o > 0; o >>= 1) {
                float ov = __shfl_down_sync(~0u, bv, o);
                int   ok = __shfl_down_sync(~0u, bk, o);
                if (ov > bv || (ov == bv && ok < bk)) { bv = ov; bk = ok; }
            }
            int wk = __shfl_sync(~0u, bk, 0);
            if (hk == wk) p++;
            if (lane == 0) {
                red[88  + warp*9 + r] = bv;
                red[160 + warp*9 + r] = __int_as_float(bk);
            }
        }
    }
    __syncthreads();   // sync 9

    // ---- Phase B: warp 0 merges 8 warp lists -> global top-9 ----
    if (warp == 0) {
        int p = 0;
        #pragma unroll
        for (int r = 0; r < 9; ++r) {
            float hv = (lane < 8 && p < 9) ? red[88 + lane*9 + p] : -2.f;
            int   hk = (lane < 8 && p < 9) ? __float_as_int(red[160 + lane*9 + p]) : 0x7fffffff;
            float bv = hv; int bk = hk;
            #pragma unroll
            for (int o = 4; o > 0; o >>= 1) {
                float ov = __shfl_down_sync(~0u, bv, o);
                int   ok = __shfl_down_sync(~0u, bk, o);
                if (ov > bv || (ov == bv && ok < bk)) { bv = ov; bk = ok; }
            }
            int wk = __shfl_sync(~0u, bk, 0);
            if (hk == wk) p++;
            if (lane == 0) {
                red[280 + r] = bv;
                red[289 + r] = __int_as_float(bk);
            }
        }
    }

    // ---- epilogue (thread 0, same warp as Phase B writes) ----
    if (tid == 0) {
        float s1 = 0.f, s2 = 0.f, s3 = 0.f, s4 = 0.f, R[5] = {0,0,0,0,0};
        float S = 0.f, maxamp = 0.f;
        #pragma unroll
        for (int i = 0; i < 8; i++) {
            s1 += red[0*8+i]; s2 += red[1*8+i]; s3 += red[2*8+i]; s4 += red[3*8+i];
            R[0] += red[4*8+i]; R[1] += red[5*8+i]; R[2] += red[6*8+i];
            R[3] += red[7*8+i]; R[4] += red[8*8+i];
            S += red[72+i]; maxamp = fmaxf(maxamp, red[80+i]);
        }
        float topv[9]; int topi[9];
        #pragma unroll
        for (int r = 0; r < 9; ++r) {
            topv[r] = red[280 + r];
            topi[r] = __float_as_int(red[289 + r]);
        }
        // edge prefix/suffix sums
        float H[25], T[25];
        H[0] = 0.f; T[0] = 0.f;
        #pragma unroll
        for (int k = 0; k < 24; k++) {
            H[k+1] = H[k] + red[232 + k];
            T[k+1] = T[k] + red[279 - k];
        }

        const float m  = s1 * (1.0f / L_);
        const float d2 = s2 - (float)L_ * m * m;
        const float d3 = s3 - 3.f*m*s2 + 2.f*(float)L_*m*m*m;
        const float d4 = s4 - 4.f*m*s3 + 6.f*m*m*s2 - 3.f*(float)L_*m*m*m*m;

        const float var  = d2 / (float)(L_ - 1);
        const float stdv = sqrtf(var);
        const float se   = stdv + 1e-8f;
        const float se2  = se * se;
        const float skew = (d3 / (float)L_) / (se * se2 + 1e-8f);
        const float kurt = (d4 / (float)L_) / (se2 * se2 + 1e-8f) - 3.0f;

        const float total = S / (float)FBINS + 1e-8f;
        float lvlsum[3] = { topv[0]+topv[1]+topv[2]+topv[3]+topv[4],
                            topv[5]+topv[6], topv[7] };
        float g[3]; float prefix = 0.f;
        #pragma unroll
        for (int l = 0; l < 3; l++) {
            float rr = ((S - prefix) / (float)FBINS) / total;
            float lr = 0.25f * (float)(l + 1);
            float o = b2v[0];
            #pragma unroll
            for (int j = 0; j < 8; j++) {
                float h = rr * w1[j] + lr * w1[8 + j] + b1v[j];
                h = 0.5f * h * (1.0f + erff(h * 0.70710678118654752f));
                o += h * w2[j];
            }
            g[l] = 1.0f / (1.0f + expf(-o));
            prefix += lvlsum[l];
        }
        const float r1 = g[0], r2 = g[0]*g[1], r3 = g[0]*g[1]*g[2];
        const float rf[9] = {1.f,1.f,1.f,1.f,1.f, r1, r1, r2, r3};
        float cv[9]; int ci[9];
        #pragma unroll
        for (int i = 0; i < 9; i++) { cv[i] = topv[i]*rf[i]; ci[i] = topi[i]; }
        for (int i = 1; i < 9; i++) {           // value desc, index asc on ties
            float v = cv[i]; int id = ci[i]; int j = i - 1;
            while (j >= 0 && (cv[j] < v || (cv[j] == v && ci[j] > id))) {
                cv[j+1] = cv[j]; ci[j+1] = ci[j]; j--;
            }
            cv[j+1] = v; ci[j+1] = id;
        }

        const float invden = 1.0f / (maxamp + 2e-8f);
        float* op = out + (size_t)blockIdx.x * 19;
        op[0] = m; op[1] = stdv; op[2] = skew; op[3] = kurt;
        #pragma unroll
        for (int i = 0; i < 5; i++) {
            op[4 + i] = (float)ci[i] * (1.0f / (float)L_);
            op[9 + i] = cv[i] * invden;
        }
        #pragma unroll
        for (int q = 0; q < 5; q++) {
            int l = lags[q];
            float acsum = R[q] - m * ((s1 - T[l]) + (s1 - H[l])) + (float)(L_ - l) * m * m;
            op[14 + q] = (acsum / (float)(L_ - l)) / se2;
        }
    }
}

// ---------------------------------------------------------------------------
extern "C" void kernel_launch(void* const* d_in, const int* in_sizes, int n_in,
                              void* d_out, int out_size) {
    const float* x  = (const float*)d_in[0];
    const float* w1 = (const float*)d_in[1];
    const float* b1 = (const float*)d_in[2];
    const float* w2 = (const float*)d_in[3];
    const float* b2 = (const float*)d_in[4];
    float* out = (float*)d_out;

    dim3 tb(32, 8);
    dim3 tg(L_ / 32, N_ / 32, B_);
    transpose_kernel<<<tg, tb>>>(x);

    feat_kernel<<<NSERIES, NT>>>(w1, b1, w2, b2, out);
}

// round 8
// speedup vs baseline: 2.0989x; 1.0143x over previous
#include <cuda_runtime.h>
#include <math.h>

#define B_ 32
#define L_ 4096
#define N_ 256
#define NF 2048          // packed complex FFT size (L/2)
#define FBINS 2049       // rfft bins
#define NT 256
#define NSERIES (B_*N_)

__device__ float  g_xt[(size_t)B_*N_*L_];   // (B,N,L) transposed input
__device__ float2 g_tw[NF/2];               // exp(-2*pi*i*j/2048)
__device__ float2 g_rot[NF];                // exp(-pi*i*k/2048)

// XOR swizzle on float2 indices: conflict-free smem FFT exchanges
#define FZ(a) ((a) ^ (((a) >> 3) & 0xF))
// padded natural-order spectrum index: writes (k = 8m+c pattern) provably
// conflict-free (addr = 9m+c mod 32, gcd(9,32)=1); consecutive-k reads ~1.12x
#define YA(k) ((k) + ((k) >> 3))

__device__ __forceinline__ float2 cmul(float2 a, float2 b) {
    return make_float2(a.x*b.x - a.y*b.y, a.x*b.y + a.y*b.x);
}
__device__ __forceinline__ float2 cadd(float2 a, float2 b) { return make_float2(a.x+b.x, a.y+b.y); }
__device__ __forceinline__ float2 csub(float2 a, float2 b) { return make_float2(a.x-b.x, a.y-b.y); }
__device__ __forceinline__ float2 cnegi(float2 a) { return make_float2(a.y, -a.x); }  // a * (-i)

// ---------------------------------------------------------------------------
// Tiled transpose x (B,L,N) -> g_xt (B,N,L); block (0,0,0) also fills twiddle tables.
__global__ void transpose_kernel(const float* __restrict__ x) {
    __shared__ float tile[32][33];
    int b  = blockIdx.z;
    int l0 = blockIdx.x << 5;
    int n0 = blockIdx.y << 5;
    int tx = threadIdx.x, ty = threadIdx.y;   // (32, 8)
    if (blockIdx.x == 0 && blockIdx.y == 0 && blockIdx.z == 0) {
        int tid = ty * 32 + tx;
        for (int i = tid; i < NF/2; i += 256) {
            float ang = -6.2831853071795864769f * (float)i / (float)NF;
            float sn, cs; sincosf(ang, &sn, &cs);
            g_tw[i] = make_float2(cs, sn);
        }
        for (int i = tid; i < NF; i += 256) {
            float ang = -3.1415926535897932385f * (float)i / (float)NF;
            float sn, cs; sincosf(ang, &sn, &cs);
            g_rot[i] = make_float2(cs, sn);
        }
    }
    #pragma unroll
    for (int i = 0; i < 32; i += 8)
        tile[ty + i][tx] = x[((size_t)b * L_ + (l0 + ty + i)) * N_ + n0 + tx];
    __syncthreads();
    #pragma unroll
    for (int i = 0; i < 32; i += 8)
        g_xt[((size_t)b * N_ + (n0 + ty + i)) * L_ + l0 + tx] = tile[tx][ty + i];
}

// ---------------------------------------------------------------------------
// radix-4 DIF butterfly (in-place digit placement), twiddles wa = w_S^o, wb = w_{S/2}^o
__device__ __forceinline__ void bfy4(float2* x, float2 wa, float2 wb) {
    float2 wami = cnegi(wa);
    float2 t0 = cadd(x[0], x[2]), u0 = cmul(csub(x[0], x[2]), wa);
    float2 t1 = cadd(x[1], x[3]), u1 = cmul(csub(x[1], x[3]), wami);
    x[0] = cadd(t0, t1); x[1] = cmul(csub(t0, t1), wb);
    x[2] = cadd(u0, u1); x[3] = cmul(csub(u0, u1), wb);
}

// radix-8 DIF butterfly = 3 in-place radix-2 stages on 8 register values.
__device__ __forceinline__ void bfy8(float2* x, float2 wa, float2 wb, float2 wc) {
    const float R2 = 0.70710678118654752440f;
    float2 wa1 = cmul(wa, make_float2(R2, -R2));
    float2 wa2 = cnegi(wa);
    float2 wa3 = cnegi(wa1);
    float2 wbi = cnegi(wb);
    float2 d;
    d = csub(x[0], x[4]); x[0] = cadd(x[0], x[4]); x[4] = cmul(d, wa);
    d = csub(x[1], x[5]); x[1] = cadd(x[1], x[5]); x[5] = cmul(d, wa1);
    d = csub(x[2], x[6]); x[2] = cadd(x[2], x[6]); x[6] = cmul(d, wa2);
    d = csub(x[3], x[7]); x[3] = cadd(x[3], x[7]); x[7] = cmul(d, wa3);
    d = csub(x[0], x[2]); x[0] = cadd(x[0], x[2]); x[2] = cmul(d, wb);
    d = csub(x[1], x[3]); x[1] = cadd(x[1], x[3]); x[3] = cmul(d, wbi);
    d = csub(x[4], x[6]); x[4] = cadd(x[4], x[6]); x[6] = cmul(d, wb);
    d = csub(x[5], x[7]); x[5] = cadd(x[5], x[7]); x[7] = cmul(d, wbi);
    d = csub(x[0], x[1]); x[0] = cadd(x[0], x[1]); x[1] = cmul(d, wc);
    d = csub(x[2], x[3]); x[2] = cadd(x[2], x[3]); x[3] = cmul(d, wc);
    d = csub(x[4], x[5]); x[4] = cadd(x[4], x[5]); x[5] = cmul(d, wc);
    d = csub(x[6], x[7]); x[6] = cadd(x[6], x[7]); x[7] = cmul(d, wc);
}

// ---------------------------------------------------------------------------
// One CTA per (b,n) series.
__global__ __launch_bounds__(NT, 4) void feat_kernel(
    const float* __restrict__ w1, const float* __restrict__ b1v,
    const float* __restrict__ w2, const float* __restrict__ b2v,
    float* __restrict__ out)
{
    __shared__ float s[4608];    // [0,4096): series / FFT z[]; later per-thread sorted lists
    __shared__ float yr[2304];   // natural-order spectrum real (YA padding)
    __shared__ float yi[2304];   // natural-order spectrum imag (YA padding)
    __shared__ float red[304];
    // red layout: [0..71] 9x8 moment partials | [72..79] ampsum | [80..87] ampmax
    //             [88..159] warp-list vals | [160..231] warp-list keys
    //             [232..255] head24 | [256..279] tail24 | [280..297] global top9

    const int tid  = threadIdx.x;
    const int lane = tid & 31, warp = tid >> 5;
    const int lags[5] = {1, 3, 6, 12, 24};

    // ---- phase 1: contiguous load, STS, raw moments in registers ----
    float xl[16];
    {
        const float4* __restrict__ src4 =
            (const float4*)(g_xt + (size_t)blockIdx.x * L_ + tid * 16);
        float4* sm4 = (float4*)s;
        #pragma unroll
        for (int c = 0; c < 4; ++c) {
            float4 v = src4[c];
            sm4[tid*4 + c] = v;
            xl[4*c+0] = v.x; xl[4*c+1] = v.y; xl[4*c+2] = v.z; xl[4*c+3] = v.w;
        }
    }
    if (tid < 8) ((float4*)s)[1024 + tid] = make_float4(0.f, 0.f, 0.f, 0.f); // zero pad

    // edge stashes (raw values) for autocorr boundary terms
    if (tid == 0) {
        for (int k = 0; k < 16; k++) red[232 + k] = xl[k];
    }
    if (tid == 1) {
        for (int k = 0; k < 8;  k++) red[248 + k] = xl[k];
    }
    if (tid == 254) {
        for (int k = 0; k < 8;  k++) red[256 + k] = xl[8 + k];
    }
    if (tid == 255) {
        for (int k = 0; k < 16; k++) red[264 + k] = xl[k];
    }

    float acc[9];   // s1 s2 s3 s4 R1 R3 R6 R12 R24 (raw sums)
    #pragma unroll
    for (int q = 0; q < 9; q++) acc[q] = 0.f;
    #pragma unroll
    for (int i = 0; i < 16; i++) {
        float v = xl[i], v2 = v*v;
        acc[0] += v; acc[1] += v2; acc[2] += v2*v; acc[3] += v2*v2;
        #pragma unroll
        for (int q = 0; q < 5; q++) {
            int j = i + lags[q];
            if (j < 16) acc[4+q] += v * xl[j];
        }
    }
    __syncthreads();   // sync 1: smem series complete (incl. zero pad)

    // cross-boundary lag products: consume tail in float4 chunks (low reg pressure)
    {
        #pragma unroll
        for (int c2 = 0; c2 < 6; ++c2) {
            float4 v = *(const float4*)(s + tid*16 + 16 + 4*c2);
            float tl4[4] = {v.x, v.y, v.z, v.w};
            #pragma unroll
            for (int q = 0; q < 5; q++) {
                int l = lags[q];
                #pragma unroll
                for (int kk = 0; kk < 4; kk++) {
                    int k = 4*c2 + kk;
                    int i = 16 + k - l;
                    if (k < l && i >= 0) acc[4+q] += xl[i] * tl4[kk];
                }
            }
        }
    }
    // warp-reduce 9 raw sums -> red partials (finalized by tid0 at the end)
    #pragma unroll
    for (int q = 0; q < 9; q++) {
        float v = acc[q];
        #pragma unroll
        for (int o = 16; o > 0; o >>= 1) v += __shfl_down_sync(~0u, v, o);
        if (lane == 0) red[q*8 + warp] = v;
    }

    // ---- FFT group 0: radix-4 (S=2048), natural read -> swizzled write ----
    float2* z = (float2*)s;
    float2 xa[4], xb[4];
    #pragma unroll
    for (int j = 0; j < 4; j++) { xa[j] = z[tid + 512*j]; xb[j] = z[tid + 256 + 512*j]; }
    bfy4(xa, g_tw[tid],       g_tw[2*tid]);
    bfy4(xb, g_tw[tid + 256], g_tw[2*tid + 512]);
    __syncthreads();   // sync 2
    #pragma unroll
    for (int j = 0; j < 4; j++) {
        z[FZ(tid + 512*j)]       = xa[j];
        z[FZ(tid + 256 + 512*j)] = xb[j];
    }
    __syncthreads();   // sync 3

    float2 zx[8];
    // ---- group 1: radix-8, S=512, q=64 ----
    {
        int o = tid & 63, base = (tid >> 6) * 512 + o;
        #pragma unroll
        for (int j = 0; j < 8; j++) zx[j] = z[FZ(base + 64*j)];
        bfy8(zx, g_tw[4*o], g_tw[8*o], g_tw[16*o]);
        #pragma unroll
        for (int j = 0; j < 8; j++) z[FZ(base + 64*j)] = zx[j];
    }
    __syncthreads();   // sync 4
    // ---- group 2: radix-8, S=64, q=8 ----
    {
        int o = tid & 7, base = (tid >> 3) * 64 + o;
        #pragma unroll
        for (int j = 0; j < 8; j++) zx[j] = z[FZ(base + 8*j)];
        bfy8(zx, g_tw[32*o], g_tw[64*o], g_tw[128*o]);
        #pragma unroll
        for (int j = 0; j < 8; j++) z[FZ(base + 8*j)] = zx[j];
    }
    __syncthreads();   // sync 5
    // ---- group 3: radix-8, S=8, q=1 (unit twiddles), FUSED de-reversal:
    //      outputs go straight to natural-order yr/yi (conflict-free stores) ----
    {
        int base = tid * 8;
        const float2 one = make_float2(1.f, 0.f);
        #pragma unroll
        for (int j = 0; j < 8; j++) zx[j] = z[FZ(base + j)];
        bfy8(zx, one, one, one);
        #pragma unroll
        for (int j = 0; j < 8; j++) {
            int k = __brev((unsigned)(base + j)) >> 21;   // natural bin
            int a = YA(k);
            yr[a] = zx[j].x; yi[a] = zx[j].y;
        }
    }
    __syncthreads();   // sync 6: yr/yi ready; all z reads done (s reusable)

    // ---- unpack amplitudes via conjugate-pair symmetry + local sort ----
    // X[k] = E + wO ; X[2048-k] = conj(E - wO)  -> two amps per pair, one rot load
    float av[9]; int ak[9];
    float Ssum = 0.f, Smax = 0.f;
    #pragma unroll
    for (int c = 0; c < 4; ++c) {
        int k = 1 + tid + 256*c;          // 1..1024
        int m = 2048 - k;                 // 1024..2047
        int ka = YA(k), ma = YA(m);
        float zkr = yr[ka], zki = yi[ka];
        float zmr = yr[ma], zmi = yi[ma];
        float er  = 0.5f * (zkr + zmr);
        float ei  = 0.5f * (zki - zmi);
        float orr = 0.5f * (zki + zmi);
        float oi  = -0.5f * (zkr - zmr);
        float2 w = g_rot[k];
        float pr = w.x*orr - w.y*oi;
        float pi = w.x*oi  + w.y*orr;
        float xr = er + pr, xi2 = ei + pi;
        float ampk = sqrtf(xr*xr + xi2*xi2);
        float qr = er - pr, qi = ei - pi;
        float ampm = sqrtf(qr*qr + qi*qi);
        av[c] = ampk; ak[c] = k;
        Ssum += ampk; Smax = fmaxf(Smax, ampk);
        if (k == 1024) { av[4+c] = -1.f; ak[4+c] = 0x3fffffff; }  // self-pair dup
        else {
            av[4+c] = ampm; ak[4+c] = m;
            Ssum += ampm; Smax = fmaxf(Smax, ampm);
        }
    }
    av[8] = -1.f; ak[8] = 0x3fffffff;

    float a0 = 0.f, aN = 0.f;
    if (tid == 0) {
        float z0r = yr[0], z0i = yi[0];   // YA(0)==0
        a0 = fabsf(z0r + z0i);            // bin 0
        aN = fabsf(z0r - z0i);            // bin 2048
        Ssum += a0 + aN;
        Smax = fmaxf(Smax, fmaxf(a0, aN));
    }

    // sort av[0..7] desc (tie -> lower index), Batcher 19 CE
    #define CE(i,j) { if (av[i] < av[j] || (av[i]==av[j] && ak[i] > ak[j])) { \
        float tv=av[i]; av[i]=av[j]; av[j]=tv; int tk=ak[i]; ak[i]=ak[j]; ak[j]=tk; } }
    CE(0,1) CE(2,3) CE(4,5) CE(6,7)
    CE(0,2) CE(1,3) CE(4,6) CE(5,7)
    CE(1,2) CE(5,6)
    CE(0,4) CE(1,5) CE(2,6) CE(3,7)
    CE(2,4) CE(3,5)
    CE(1,2) CE(3,4) CE(5,6)
    // tid0: insert bins 0 and 2048 (insert-with-drop keeps thread top-9)
    if (tid == 0) {
        if (a0 > av[8] || (a0 == av[8] && 0 < ak[8])) { av[8] = a0; ak[8] = 0; }
        CE(7,8) CE(6,7) CE(5,6) CE(4,5) CE(3,4) CE(2,3) CE(1,2) CE(0,1)
        if (aN > av[8] || (aN == av[8] && 2048 < ak[8])) { av[8] = aN; ak[8] = 2048; }
        CE(7,8) CE(6,7) CE(5,6) CE(4,5) CE(3,4) CE(2,3) CE(1,2) CE(0,1)
    } else {
        CE(7,8) CE(6,7) CE(5,6) CE(4,5) CE(3,4) CE(2,3) CE(1,2) CE(0,1)
    }
    #undef CE

    // amp sum/max warp partials
    {
        float sv = Ssum, mv = Smax;
        #pragma unroll
        for (int o = 16; o > 0; o >>= 1) {
            sv += __shfl_down_sync(~0u, sv, o);
            mv = fmaxf(mv, __shfl_down_sync(~0u, mv, o));
        }
        if (lane == 0) { red[72 + warp] = sv; red[80 + warp] = mv; }
    }

    // spill per-thread sorted lists into s (s dead since sync 6; each thread
    // writes + later reads only its own slots — no barrier needed for Phase A)
    #pragma unroll
    for (int r = 0; r < 9; ++r) {
        s[tid*9 + r]        = av[r];
        s[2304 + tid*9 + r] = __int_as_float(ak[r]);
    }

    // ---- Phase A: warp-local tournament -> warp top-9 (reads own list only) ----
    {
        int p = 0;
        #pragma unroll
        for (int r = 0; r < 9; ++r) {
            float hv = (p < 9) ? s[tid*9 + p] : -2.f;
            int   hk = (p < 9) ? __float_as_int(s[2304 + tid*9 + p]) : 0x7fffffff;
            float bv = hv; int bk = hk;
            #pragma unroll
            for (int o = 16; o > 0; o >>= 1) {
                float ov = __shfl_down_sync(~0u, bv, o);
                int   ok = __shfl_down_sync(~0u, bk, o);
                if (ov > bv || (ov == bv && ok < bk)) { bv = ov; bk = ok; }
            }
            int wk = __shfl_sync(~0u, bk, 0);
            if (hk == wk) p++;
            if (lane == 0) {
                red[88  + warp*9 + r] = bv;
                red[160 + warp*9 + r] = __int_as_float(bk);
            }
        }
    }
    __syncthreads();   // sync 7: warp winners + amp partials visible

    // ---- Phase B: warp 0 merges 8 warp lists -> global top-9 ----
    if (warp == 0) {
        int p = 0;
        #pragma unroll
        for (int r = 0; r < 9; ++r) {
            float hv = (lane < 8 && p < 9) ? red[88 + lane*9 + p] : -2.f;
            int   hk = (lane < 8 && p < 9) ? __float_as_int(red[160 + lane*9 + p]) : 0x7fffffff;
            float bv = hv; int bk = hk;
            #pragma unroll
            for (int o = 4; o > 0; o >>= 1) {
                float ov = __shfl_down_sync(~0u, bv, o);
                int   ok = __shfl_down_sync(~0u, bk, o);
                if (ov > bv || (ov == bv && ok < bk)) { bv = ov; bk = ok; }
            }
            int wk = __shfl_sync(~0u, bk, 0);
            if (hk == wk) p++;
            if (lane == 0) {
                red[280 + r] = bv;
                red[289 + r] = __int_as_float(bk);
            }
        }
    }

    // ---- epilogue (thread 0, same warp as Phase B writes) ----
    if (tid == 0) {
        float s1 = 0.f, s2 = 0.f, s3 = 0.f, s4 = 0.f, R[5] = {0,0,0,0,0};
        float S = 0.f, maxamp = 0.f;
        #pragma unroll
        for (int i = 0; i < 8; i++) {
            s1 += red[0*8+i]; s2 += red[1*8+i]; s3 += red[2*8+i]; s4 += red[3*8+i];
            R[0] += red[4*8+i]; R[1] += red[5*8+i]; R[2] += red[6*8+i];
            R[3] += red[7*8+i]; R[4] += red[8*8+i];
            S += red[72+i]; maxamp = fmaxf(maxamp, red[80+i]);
        }
        float topv[9]; int topi[9];
        #pragma unroll
        for (int r = 0; r < 9; ++r) {
            topv[r] = red[280 + r];
            topi[r] = __float_as_int(red[289 + r]);
        }
        // edge prefix/suffix sums
        float H[25], T[25];
        H[0] = 0.f; T[0] = 0.f;
        #pragma unroll
        for (int k = 0; k < 24; k++) {
            H[k+1] = H[k] + red[232 + k];
            T[k+1] = T[k] + red[279 - k];
        }

        const float m  = s1 * (1.0f / L_);
        const float d2 = s2 - (float)L_ * m * m;
        const float d3 = s3 - 3.f*m*s2 + 2.f*(float)L_*m*m*m;
        const float d4 = s4 - 4.f*m*s3 + 6.f*m*m*s2 - 3.f*(float)L_*m*m*m*m;

        const float var  = d2 / (float)(L_ - 1);
        const float stdv = sqrtf(var);
        const float se   = stdv + 1e-8f;
        const float se2  = se * se;
        const float skew = (d3 / (float)L_) / (se * se2 + 1e-8f);
        const float kurt = (d4 / (float)L_) / (se2 * se2 + 1e-8f) - 3.0f;

        const float total = S / (float)FBINS + 1e-8f;
        float lvlsum[3] = { topv[0]+topv[1]+topv[2]+topv[3]+topv[4],
                            topv[5]+topv[6], topv[7] };
        float g[3]; float prefix = 0.f;
        #pragma unroll
        for (int l = 0; l < 3; l++) {
            float rr = ((S - prefix) / (float)FBINS) / total;
            float lr = 0.25f * (float)(l + 1);
            float o = b2v[0];
            #pragma unroll
            for (int j = 0; j < 8; j++) {
                float h = rr * w1[j] + lr * w1[8 + j] + b1v[j];
                h = 0.5f * h * (1.0f + erff(h * 0.70710678118654752f));
                o += h * w2[j];
            }
            g[l] = 1.0f / (1.0f + expf(-o));
            prefix += lvlsum[l];
        }
        const float r1 = g[0], r2 = g[0]*g[1], r3 = g[0]*g[1]*g[2];
        const float rf[9] = {1.f,1.f,1.f,1.f,1.f, r1, r1, r2, r3};
        float cv[9]; int ci[9];
        #pragma unroll
        for (int i = 0; i < 9; i++) { cv[i] = topv[i]*rf[i]; ci[i] = topi[i]; }
        for (int i = 1; i < 9; i++) {           // value desc, index asc on ties
            float v = cv[i]; int id = ci[i]; int j = i - 1;
            while (j >= 0 && (cv[j] < v || (cv[j] == v && ci[j] > id))) {
                cv[j+1] = cv[j]; ci[j+1] = ci[j]; j--;
            }
            cv[j+1] = v; ci[j+1] = id;
        }

        const float invden = 1.0f / (maxamp + 2e-8f);
        float* op = out + (size_t)blockIdx.x * 19;
        op[0] = m; op[1] = stdv; op[2] = skew; op[3] = kurt;
        #pragma unroll
        for (int i = 0; i < 5; i++) {
            op[4 + i] = (float)ci[i] * (1.0f / (float)L_);
            op[9 + i] = cv[i] * invden;
        }
        #pragma unroll
        for (int q = 0; q < 5; q++) {
            int l = lags[q];
            float acsum = R[q] - m * ((s1 - T[l]) + (s1 - H[l])) + (float)(L_ - l) * m * m;
            op[14 + q] = (acsum / (float)(L_ - l)) / se2;
        }
    }
}

// ---------------------------------------------------------------------------
extern "C" void kernel_launch(void* const* d_in, const int* in_sizes, int n_in,
                              void* d_out, int out_size) {
    const float* x  = (const float*)d_in[0];
    const float* w1 = (const float*)d_in[1];
    const float* b1 = (const float*)d_in[2];
    const float* w2 = (const float*)d_in[3];
    const float* b2 = (const float*)d_in[4];
    float* out = (float*)d_out;

    dim3 tb(32, 8);
    dim3 tg(L_ / 32, N_ / 32, B_);
    transpose_kernel<<<tg, tb>>>(x);

    feat_kernel<<<NSERIES, NT>>>(w1, b1, w2, b2, out);
}